// round 6
// baseline (speedup 1.0000x reference)
#include <cuda_runtime.h>
#include <cuda_bf16.h>
#include <math.h>
#include <stdint.h>

#define BQ 8
#define TQ 2048
#define DQ 512
#define NTOK (BQ * TQ)            // 16384
#define GRU_CTAS 128

// ---------------- scratch (device globals; allocation-free) ----------------
__device__ float g_short[NTOK * DQ];
__device__ float g_mid[NTOK * DQ];
__device__ float g_long[NTOK * DQ];
__device__ float g_memc[NTOK * DQ];
__device__ float g_change[NTOK * DQ];
__device__ float g_fused[NTOK * DQ];
__device__ float g_xg[NTOK * 3 * DQ];
__device__ float g_h1[NTOK * 256];
__device__ float g_fh[NTOK * 1024];
__device__ float g_hbuf[2][BQ * DQ];
__device__ unsigned g_flag[GRU_CTAS];

struct SegPtrs { const float* p[5]; };

// ---------------- helpers ----------------
__device__ __forceinline__ float gelu_exact(float x) {
    return 0.5f * x * (1.0f + erff(x * 0.70710678118654752440f));
}

#define FMA2(d, a, b) asm("fma.rn.f32x2 %0, %1, %2, %0;" : "+l"(d) : "l"(a), "l"(b))

__device__ __forceinline__ unsigned long long pack2(float x, float y) {
    unsigned long long r;
    asm("mov.b64 %0, {%1, %2};" : "=l"(r) : "r"(__float_as_uint(x)), "r"(__float_as_uint(y)));
    return r;
}
__device__ __forceinline__ void unpack2(unsigned long long v, float& x, float& y) {
    unsigned lo, hi;
    asm("mov.b64 {%0, %1}, %2;" : "=r"(lo), "=r"(hi) : "l"(v));
    x = __uint_as_float(lo); y = __uint_as_float(hi);
}

__device__ __forceinline__ float block_sum_512(float v, float* red) {
    int lane = threadIdx.x & 31, w = threadIdx.x >> 5;
    #pragma unroll
    for (int off = 16; off > 0; off >>= 1) v += __shfl_xor_sync(0xffffffffu, v, off);
    if (lane == 0) red[w] = v;
    __syncthreads();
    float s = (threadIdx.x < 16) ? red[threadIdx.x] : 0.0f;
    if (w == 0) {
        #pragma unroll
        for (int off = 8; off > 0; off >>= 1) s += __shfl_xor_sync(0xffffffffu, s, off);
        if (lane == 0) red[0] = s;
    }
    __syncthreads();
    float r = red[0];
    __syncthreads();
    return r;
}

__device__ __forceinline__ uint32_t smem_u32(const void* p) {
    return (uint32_t)__cvta_generic_to_shared(p);
}

#define LDSM4(r0, r1, r2, r3, addr) \
    asm volatile("ldmatrix.sync.aligned.m8n8.x4.shared.b16 {%0,%1,%2,%3},[%4];" \
                 : "=r"(r0), "=r"(r1), "=r"(r2), "=r"(r3) : "r"(addr))

#define MMA16816(d, a, b) \
    asm volatile("mma.sync.aligned.m16n8k16.row.col.f32.bf16.bf16.f32 " \
                 "{%0,%1,%2,%3},{%4,%5,%6,%7},{%8,%9},{%0,%1,%2,%3};" \
                 : "+f"((d)[0]), "+f"((d)[1]), "+f"((d)[2]), "+f"((d)[3]) \
                 : "r"((a)[0]), "r"((a)[1]), "r"((a)[2]), "r"((a)[3]), \
                   "r"((b)[0]), "r"((b)[1]))

__device__ __forceinline__ void split4(float4 v, __nv_bfloat16* hi, __nv_bfloat16* lo) {
    float x[4] = {v.x, v.y, v.z, v.w};
    #pragma unroll
    for (int i = 0; i < 4; i++) {
        __nv_bfloat16 h = __float2bfloat16(x[i]);
        hi[i] = h;
        lo[i] = __float2bfloat16(x[i] - __bfloat162float(h));
    }
}

// ---------------- conv (3 scales) + per-scale LN, fused ----------------
__global__ void ctx_kernel(const float* __restrict__ emb,
                           const float* __restrict__ w_s, const float* __restrict__ b_s,
                           const float* __restrict__ g_s, const float* __restrict__ be_s,
                           const float* __restrict__ w_m, const float* __restrict__ b_m,
                           const float* __restrict__ g_m, const float* __restrict__ be_m,
                           const float* __restrict__ w_l, const float* __restrict__ b_l,
                           const float* __restrict__ g_l, const float* __restrict__ be_l,
                           float* __restrict__ out_s, float* __restrict__ out_m,
                           float* __restrict__ out_l) {
    __shared__ float red[16];
    const int token = blockIdx.x;
    const int t = token & (TQ - 1);
    const int d = threadIdx.x;

    float xr[32];
    #pragma unroll
    for (int j = 0; j < 32; j++)
        xr[j] = (t - j >= 0) ? emb[((size_t)(token - j)) * DQ + d] : 0.0f;

    float ys = b_s[d], ym = b_m[d], yl = b_l[d];
    #pragma unroll
    for (int j = 0; j < 2; j++)  ys += w_s[d * 2 + 1 - j] * xr[j];
    #pragma unroll
    for (int j = 0; j < 8; j++)  ym += w_m[d * 8 + 7 - j] * xr[j];
    #pragma unroll
    for (int j = 0; j < 32; j++) yl += w_l[d * 32 + 31 - j] * xr[j];

    const size_t base = (size_t)token * DQ + d;
    {
        float mu = block_sum_512(ys, red) * (1.0f / DQ);
        float dv = ys - mu;
        float var = block_sum_512(dv * dv, red) * (1.0f / DQ);
        out_s[base] = dv * rsqrtf(var + 1e-5f) * g_s[d] + be_s[d];
    }
    {
        float mu = block_sum_512(ym, red) * (1.0f / DQ);
        float dv = ym - mu;
        float var = block_sum_512(dv * dv, red) * (1.0f / DQ);
        out_m[base] = dv * rsqrtf(var + 1e-5f) * g_m[d] + be_m[d];
    }
    {
        float mu = block_sum_512(yl, red) * (1.0f / DQ);
        float dv = yl - mu;
        float var = block_sum_512(dv * dv, red) * (1.0f / DQ);
        out_l[base] = dv * rsqrtf(var + 1e-5f) * g_l[d] + be_l[d];
    }
}

// ============================================================================
// Tensor-core GEMM: C[M,N] = A[M,K] @ W[N,K]^T + bias (opt GELU), fp32 I/O.
// bf16 3-pass split (A=hi+lo, W=hi+lo; acc += AhWh + AhWl + AlWh).
// BM=BN=128, BK=32, 256 threads (8 warps: 4x2), warp tile 32x64.
// ============================================================================
struct GemmSmem {
    __nv_bfloat16 Ah[128][40];
    __nv_bfloat16 Al[128][40];
    __nv_bfloat16 Bh[128][40];
    __nv_bfloat16 Bl[128][40];
};

__device__ __forceinline__ void gemm_mainloop_k32(
    GemmSmem& sm, float acc[2][8][4], int warp_m, int warp_n, int lane) {
    #pragma unroll
    for (int ks = 0; ks < 32; ks += 16) {
        const int arow = (lane & 15);
        const int acol = ks + (lane >> 4) * 8;
        uint32_t ah[2][4], al[2][4];
        #pragma unroll
        for (int mi = 0; mi < 2; mi++) {
            int mb = warp_m * 32 + mi * 16;
            uint32_t addr_h = smem_u32(&sm.Ah[mb + arow][acol]);
            uint32_t addr_l = smem_u32(&sm.Al[mb + arow][acol]);
            LDSM4(ah[mi][0], ah[mi][1], ah[mi][2], ah[mi][3], addr_h);
            LDSM4(al[mi][0], al[mi][1], al[mi][2], al[mi][3], addr_l);
        }
        #pragma unroll
        for (int pair = 0; pair < 4; pair++) {
            int nb = warp_n * 64 + pair * 16;
            uint32_t bh[4], bl[4];
            uint32_t baddr_h = smem_u32(&sm.Bh[nb + arow][acol]);
            uint32_t baddr_l = smem_u32(&sm.Bl[nb + arow][acol]);
            LDSM4(bh[0], bh[1], bh[2], bh[3], baddr_h);
            LDSM4(bl[0], bl[1], bl[2], bl[3], baddr_l);
            uint32_t bEh[2] = {bh[0], bh[2]}, bOh[2] = {bh[1], bh[3]};
            uint32_t bEl[2] = {bl[0], bl[2]}, bOl[2] = {bl[1], bl[3]};
            #pragma unroll
            for (int mi = 0; mi < 2; mi++) {
                MMA16816(acc[mi][2 * pair],     ah[mi], bEh);
                MMA16816(acc[mi][2 * pair],     ah[mi], bEl);
                MMA16816(acc[mi][2 * pair],     al[mi], bEh);
                MMA16816(acc[mi][2 * pair + 1], ah[mi], bOh);
                MMA16816(acc[mi][2 * pair + 1], ah[mi], bOl);
                MMA16816(acc[mi][2 * pair + 1], al[mi], bOh);
            }
        }
    }
}

template <bool GELU>
__device__ __forceinline__ void gemm_epilogue(
    float acc[2][8][4], const float* __restrict__ bias, float* __restrict__ C,
    int N, int m0, int n0, int warp_m, int warp_n, int lane) {
    const int g = lane >> 2, tg = lane & 3;
    #pragma unroll
    for (int mi = 0; mi < 2; mi++) {
        #pragma unroll
        for (int ni = 0; ni < 8; ni++) {
            int row = m0 + warp_m * 32 + mi * 16 + g;
            int col = n0 + warp_n * 64 + ni * 8 + tg * 2;
            float b0 = bias[col], b1 = bias[col + 1];
            float v0 = acc[mi][ni][0] + b0, v1 = acc[mi][ni][1] + b1;
            float v2 = acc[mi][ni][2] + b0, v3 = acc[mi][ni][3] + b1;
            if (GELU) {
                v0 = gelu_exact(v0); v1 = gelu_exact(v1);
                v2 = gelu_exact(v2); v3 = gelu_exact(v3);
            }
            *reinterpret_cast<float2*>(&C[(size_t)row * N + col]) = make_float2(v0, v1);
            *reinterpret_cast<float2*>(&C[(size_t)(row + 8) * N + col]) = make_float2(v2, v3);
        }
    }
}

template <bool GELU>
__global__ __launch_bounds__(256)
void gemm_bf16_kernel(const float* __restrict__ A, const float* __restrict__ W,
                      const float* __restrict__ bias, float* __restrict__ C,
                      int M, int N, int K) {
    __shared__ GemmSmem sm;
    const int tid = threadIdx.x;
    const int lane = tid & 31, wid = tid >> 5;
    const int warp_m = wid >> 1, warp_n = wid & 1;
    const int m0 = blockIdx.y * 128, n0 = blockIdx.x * 128;

    float acc[2][8][4];
    #pragma unroll
    for (int mi = 0; mi < 2; mi++)
        #pragma unroll
        for (int ni = 0; ni < 8; ni++)
            #pragma unroll
            for (int j = 0; j < 4; j++) acc[mi][ni][j] = 0.0f;

    for (int k0 = 0; k0 < K; k0 += 32) {
        #pragma unroll
        for (int v = 0; v < 4; v++) {
            int f = v * 256 + tid;
            int r = f >> 3, c4 = (f & 7) << 2;
            float4 av = *reinterpret_cast<const float4*>(A + (size_t)(m0 + r) * K + k0 + c4);
            split4(av, &sm.Ah[r][c4], &sm.Al[r][c4]);
            float4 bv = *reinterpret_cast<const float4*>(W + (size_t)(n0 + r) * K + k0 + c4);
            split4(bv, &sm.Bh[r][c4], &sm.Bl[r][c4]);
        }
        __syncthreads();
        gemm_mainloop_k32(sm, acc, warp_m, warp_n, lane);
        __syncthreads();
    }
    gemm_epilogue<GELU>(acc, bias, C, N, m0, n0, warp_m, warp_n, lane);
}

// Segmented variant: logical A = concat of 512-wide segments (no copy buffer).
template <bool GELU, bool PREV>
__global__ __launch_bounds__(256)
void seg_gemm_bf16_kernel(SegPtrs segs, const float* __restrict__ W,
                          const float* __restrict__ bias, float* __restrict__ C,
                          int M, int N, int K) {
    __shared__ GemmSmem sm;
    const int tid = threadIdx.x;
    const int lane = tid & 31, wid = tid >> 5;
    const int warp_m = wid >> 1, warp_n = wid & 1;
    const int m0 = blockIdx.y * 128, n0 = blockIdx.x * 128;

    float acc[2][8][4];
    #pragma unroll
    for (int mi = 0; mi < 2; mi++)
        #pragma unroll
        for (int ni = 0; ni < 8; ni++)
            #pragma unroll
            for (int j = 0; j < 4; j++) acc[mi][ni][j] = 0.0f;

    for (int k0 = 0; k0 < K; k0 += 32) {
        const int seg = k0 >> 9;
        const int ks = k0 & 511;
        const float* __restrict__ Aseg = segs.p[seg];
        #pragma unroll
        for (int v = 0; v < 4; v++) {
            int f = v * 256 + tid;
            int r = f >> 3, c4 = (f & 7) << 2;
            int m = m0 + r;
            if (PREV && seg == 1) m = ((m & (TQ - 1)) == 0) ? m : m - 1;
            float4 av = *reinterpret_cast<const float4*>(Aseg + (size_t)m * DQ + ks + c4);
            split4(av, &sm.Ah[r][c4], &sm.Al[r][c4]);
            float4 bv = *reinterpret_cast<const float4*>(W + (size_t)(n0 + r) * K + k0 + c4);
            split4(bv, &sm.Bh[r][c4], &sm.Bl[r][c4]);
        }
        __syncthreads();
        gemm_mainloop_k32(sm, acc, warp_m, warp_n, lane);
        __syncthreads();
    }
    gemm_epilogue<GELU>(acc, bias, C, N, m0, n0, warp_m, warp_n, lane);
}

// ---------------- GRU persistent kernel ----------------
__device__ __forceinline__ unsigned ld_acq(const unsigned* p) {
    unsigned v;
    asm volatile("ld.acquire.gpu.global.u32 %0, [%1];" : "=r"(v) : "l"(p));
    return v;
}
__device__ __forceinline__ void st_rel(unsigned* p, unsigned v) {
    asm volatile("st.release.gpu.global.u32 [%0], %1;" :: "l"(p), "r"(v));
}

__global__ void __launch_bounds__(256)
gru_kernel(const float* __restrict__ xg, const float* __restrict__ W_hh,
           const float* __restrict__ b_hh, float* __restrict__ memc) {
    __shared__ float h_sh[BQ * DQ];
    __shared__ float hg_sh[BQ * 12];

    const int tid = threadIdx.x;
    const int w = tid >> 5, lane = tid & 31;
    const int bp = w & 1, rh = w >> 1;
    const int d0 = blockIdx.x * 4;

    unsigned long long wreg[3][8];
    #pragma unroll
    for (int rl = 0; rl < 3; rl++) {
        int lr = rh * 3 + rl;
        int grow = (lr >> 2) * DQ + d0 + (lr & 3);
        const float* wp = W_hh + (size_t)grow * DQ;
        #pragma unroll
        for (int j = 0; j < 8; j++) {
            float2 v = *reinterpret_cast<const float2*>(wp + j * 64 + lane * 2);
            wreg[rl][j] = pack2(v.x, v.y);
        }
    }

    for (int t = 0; t < TQ; t++) {
        const float* hin = g_hbuf[t & 1];
        float* hout = g_hbuf[(t + 1) & 1];

        const float4* hp = reinterpret_cast<const float4*>(hin);
        #pragma unroll
        for (int v = 0; v < 4; v++)
            reinterpret_cast<float4*>(h_sh)[tid + v * 256] = hp[tid + v * 256];

        float xr = 0.f, xz = 0.f, xn = 0.f;
        if (tid < 32) {
            int b = tid >> 2, i = tid & 3;
            size_t base = ((size_t)(b * TQ + t)) * (3 * DQ) + d0 + i;
            xr = xg[base];
            xz = xg[base + DQ];
            xn = xg[base + 2 * DQ];
        }
        __syncthreads();

        unsigned long long acc[3][4];
        #pragma unroll
        for (int rl = 0; rl < 3; rl++)
            #pragma unroll
            for (int bb = 0; bb < 4; bb++) acc[rl][bb] = 0ull;

        #pragma unroll
        for (int j = 0; j < 8; j++) {
            unsigned long long h2[4];
            #pragma unroll
            for (int bb = 0; bb < 4; bb++)
                h2[bb] = *reinterpret_cast<const unsigned long long*>(
                    &h_sh[(bp * 4 + bb) * DQ + j * 64 + lane * 2]);
            #pragma unroll
            for (int rl = 0; rl < 3; rl++)
                #pragma unroll
                for (int bb = 0; bb < 4; bb++)
                    FMA2(acc[rl][bb], h2[bb], wreg[rl][j]);
        }

        #pragma unroll
        for (int rl = 0; rl < 3; rl++)
            #pragma unroll
            for (int bb = 0; bb < 4; bb++) {
                float x, y;
                unpack2(acc[rl][bb], x, y);
                float s = x + y;
                #pragma unroll
                for (int off = 16; off > 0; off >>= 1)
                    s += __shfl_xor_sync(0xffffffffu, s, off);
                if (lane == 0) hg_sh[(bp * 4 + bb) * 12 + rh * 3 + rl] = s;
            }
        __syncthreads();

        if (tid < 32) {
            int b = tid >> 2, i = tid & 3;
            int d = d0 + i;
            float hr = hg_sh[b * 12 + i]     + b_hh[d];
            float hz = hg_sh[b * 12 + 4 + i] + b_hh[DQ + d];
            float hn = hg_sh[b * 12 + 8 + i] + b_hh[2 * DQ + d];
            float r = 1.0f / (1.0f + expf(-(xr + hr)));
            float z = 1.0f / (1.0f + expf(-(xz + hz)));
            float n = tanhf(xn + r * hn);
            float hold = h_sh[b * DQ + d];
            float hnew = (1.0f - z) * n + z * hold;
            hout[b * DQ + d] = hnew;
            memc[((size_t)(b * TQ + t)) * DQ + d] = hnew;
        }
        __syncthreads();

        // arrive: one release store per CTA (parallel, independent addresses)
        if (tid == 0) st_rel(&g_flag[blockIdx.x], (unsigned)(t + 1));
        // wait: warp 0 polls all 128 flags (4 scalar acquire loads per lane)
        if (tid < 32) {
            const unsigned* fp = g_flag + tid * 4;
            for (;;) {
                unsigned v0 = ld_acq(fp + 0);
                unsigned v1 = ld_acq(fp + 1);
                unsigned v2 = ld_acq(fp + 2);
                unsigned v3 = ld_acq(fp + 3);
                unsigned m0v = v0 < v1 ? v0 : v1;
                unsigned m1v = v2 < v3 ? v2 : v3;
                unsigned mn = m0v < m1v ? m0v : m1v;
                if (__all_sync(0xffffffffu, mn >= (unsigned)(t + 1))) break;
            }
        }
        __syncthreads();
    }
}

__global__ void reset_kernel() {
    int tid = threadIdx.x;
    for (int i = tid; i < BQ * DQ; i += blockDim.x) {
        g_hbuf[0][i] = 0.0f;
        g_hbuf[1][i] = 0.0f;
    }
    if (tid < GRU_CTAS) g_flag[tid] = 0u;
}

// ---------------- final residual + LN ----------------
__global__ void final_kernel(const float* __restrict__ emb, const float* __restrict__ fused,
                             const float* __restrict__ change,
                             const float* __restrict__ ln_g, const float* __restrict__ ln_b,
                             float* __restrict__ out) {
    __shared__ float red[16];
    const int token = blockIdx.x;
    const int d = threadIdx.x;
    const size_t base = (size_t)token * DQ + d;
    float x = emb[base] + fused[base] + change[base];
    float mu = block_sum_512(x, red) * (1.0f / DQ);
    float dv = x - mu;
    float var = block_sum_512(dv * dv, red) * (1.0f / DQ);
    out[base] = dv * rsqrtf(var + 1e-5f) * ln_g[d] + ln_b[d];
}

// ---------------- launch ----------------
static float* symp(const void* sym) {
    void* p = nullptr;
    cudaGetSymbolAddress(&p, sym);
    return (float*)p;
}

extern "C" void kernel_launch(void* const* d_in, const int* in_sizes, int n_in,
                              void* d_out, int out_size) {
    const float* emb   = (const float*)d_in[0];
    const float* w_s   = (const float*)d_in[1];
    const float* b_s   = (const float*)d_in[2];
    const float* gs    = (const float*)d_in[3];
    const float* bes   = (const float*)d_in[4];
    const float* w_m   = (const float*)d_in[5];
    const float* b_m   = (const float*)d_in[6];
    const float* gm    = (const float*)d_in[7];
    const float* bem   = (const float*)d_in[8];
    const float* w_l   = (const float*)d_in[9];
    const float* b_l   = (const float*)d_in[10];
    const float* gl    = (const float*)d_in[11];
    const float* bel   = (const float*)d_in[12];
    const float* W_ih  = (const float*)d_in[13];
    const float* W_hh  = (const float*)d_in[14];
    const float* b_ih  = (const float*)d_in[15];
    const float* b_hh  = (const float*)d_in[16];
    const float* ce_w1 = (const float*)d_in[17];
    const float* ce_b1 = (const float*)d_in[18];
    const float* ce_w2 = (const float*)d_in[19];
    const float* ce_b2 = (const float*)d_in[20];
    const float* fu_w1 = (const float*)d_in[21];
    const float* fu_b1 = (const float*)d_in[22];
    const float* fu_w2 = (const float*)d_in[23];
    const float* fu_b2 = (const float*)d_in[24];
    const float* ln_g  = (const float*)d_in[25];
    const float* ln_b  = (const float*)d_in[26];

    float* sctx   = symp(g_short);
    float* mctx   = symp(g_mid);
    float* lctx   = symp(g_long);
    float* memc   = symp(g_memc);
    float* change = symp(g_change);
    float* fused  = symp(g_fused);
    float* xg     = symp(g_xg);
    float* h1     = symp(g_h1);
    float* fh     = symp(g_fh);

    // multi-scale conv + LN
    ctx_kernel<<<NTOK, 512>>>(emb, w_s, b_s, gs, bes, w_m, b_m, gm, bem,
                              w_l, b_l, gl, bel, sctx, mctx, lctx);

    // xg = emb @ W_ih^T + b_ih   (M=16384, N=1536, K=512)
    gemm_bf16_kernel<false><<<dim3(12, 128), 256>>>(emb, W_ih, b_ih, xg, NTOK, 1536, 512);

    // change path
    {
        SegPtrs sp{};
        sp.p[0] = emb; sp.p[1] = emb;
        seg_gemm_bf16_kernel<true, true><<<dim3(2, 128), 256>>>(sp, ce_w1, ce_b1, h1,
                                                                NTOK, 256, 1024);
    }
    gemm_bf16_kernel<false><<<dim3(4, 128), 256>>>(h1, ce_w2, ce_b2, change, NTOK, 512, 256);

    // GRU recurrence
    reset_kernel<<<1, 256>>>();
    gru_kernel<<<GRU_CTAS, 256>>>(xg, W_hh, b_hh, memc);

    // fusion path
    {
        SegPtrs sp{};
        sp.p[0] = emb; sp.p[1] = sctx; sp.p[2] = mctx; sp.p[3] = lctx; sp.p[4] = memc;
        seg_gemm_bf16_kernel<true, false><<<dim3(8, 128), 256>>>(sp, fu_w1, fu_b1, fh,
                                                                 NTOK, 1024, 2560);
    }
    gemm_bf16_kernel<false><<<dim3(4, 128), 256>>>(fh, fu_w2, fu_b2, fused, NTOK, 512, 1024);

    // out = LN(emb + fused + change)
    final_kernel<<<NTOK, 512>>>(emb, fused, change, ln_g, ln_b, (float*)d_out);
}

// round 7
// speedup vs baseline: 1.7263x; 1.7263x over previous
#include <cuda_runtime.h>
#include <cuda_bf16.h>
#include <math.h>
#include <stdint.h>

#define BQ 8
#define TQ 2048
#define DQ 512
#define NTOK (BQ * TQ)            // 16384
#define GRU_CTAS 128

// ---------------- scratch (device globals; allocation-free) ----------------
__device__ float g_short[NTOK * DQ];
__device__ float g_mid[NTOK * DQ];
__device__ float g_long[NTOK * DQ];
__device__ float g_memc[NTOK * DQ];
__device__ float g_change[NTOK * DQ];
__device__ float g_fused[NTOK * DQ];
__device__ float g_xg[NTOK * 3 * DQ];
__device__ float g_h1[NTOK * 256];
__device__ float g_fh[NTOK * 1024];
__device__ float g_hbuf[2][BQ * DQ];
__device__ unsigned g_grp[16];              // tree barrier: 16 groups of 8 CTAs
__device__ unsigned g_root;
__device__ volatile unsigned g_sense;

struct SegPtrs { const float* p[5]; };

// ---------------- helpers ----------------
__device__ __forceinline__ float gelu_exact(float x) {
    return 0.5f * x * (1.0f + erff(x * 0.70710678118654752440f));
}

#define FMA2(d, a, b) asm("fma.rn.f32x2 %0, %1, %2, %0;" : "+l"(d) : "l"(a), "l"(b))

__device__ __forceinline__ unsigned long long pack2(float x, float y) {
    unsigned long long r;
    asm("mov.b64 %0, {%1, %2};" : "=l"(r) : "r"(__float_as_uint(x)), "r"(__float_as_uint(y)));
    return r;
}
__device__ __forceinline__ void unpack2(unsigned long long v, float& x, float& y) {
    unsigned lo, hi;
    asm("mov.b64 {%0, %1}, %2;" : "=r"(lo), "=r"(hi) : "l"(v));
    x = __uint_as_float(lo); y = __uint_as_float(hi);
}

__device__ __forceinline__ float block_sum_512(float v, float* red) {
    int lane = threadIdx.x & 31, w = threadIdx.x >> 5;
    #pragma unroll
    for (int off = 16; off > 0; off >>= 1) v += __shfl_xor_sync(0xffffffffu, v, off);
    if (lane == 0) red[w] = v;
    __syncthreads();
    float s = (threadIdx.x < 16) ? red[threadIdx.x] : 0.0f;
    if (w == 0) {
        #pragma unroll
        for (int off = 8; off > 0; off >>= 1) s += __shfl_xor_sync(0xffffffffu, s, off);
        if (lane == 0) red[0] = s;
    }
    __syncthreads();
    float r = red[0];
    __syncthreads();
    return r;
}

__device__ __forceinline__ uint32_t smem_u32(const void* p) {
    return (uint32_t)__cvta_generic_to_shared(p);
}

#define LDSM4(r0, r1, r2, r3, addr) \
    asm volatile("ldmatrix.sync.aligned.m8n8.x4.shared.b16 {%0,%1,%2,%3},[%4];" \
                 : "=r"(r0), "=r"(r1), "=r"(r2), "=r"(r3) : "r"(addr))

#define MMA16816(d, a, b) \
    asm volatile("mma.sync.aligned.m16n8k16.row.col.f32.bf16.bf16.f32 " \
                 "{%0,%1,%2,%3},{%4,%5,%6,%7},{%8,%9},{%0,%1,%2,%3};" \
                 : "+f"((d)[0]), "+f"((d)[1]), "+f"((d)[2]), "+f"((d)[3]) \
                 : "r"((a)[0]), "r"((a)[1]), "r"((a)[2]), "r"((a)[3]), \
                   "r"((b)[0]), "r"((b)[1]))

__device__ __forceinline__ void split4(float4 v, __nv_bfloat16* hi, __nv_bfloat16* lo) {
    float x[4] = {v.x, v.y, v.z, v.w};
    #pragma unroll
    for (int i = 0; i < 4; i++) {
        __nv_bfloat16 h = __float2bfloat16(x[i]);
        hi[i] = h;
        lo[i] = __float2bfloat16(x[i] - __bfloat162float(h));
    }
}

// ---------------- conv (3 scales) + per-scale LN, fused ----------------
__global__ void ctx_kernel(const float* __restrict__ emb,
                           const float* __restrict__ w_s, const float* __restrict__ b_s,
                           const float* __restrict__ g_s, const float* __restrict__ be_s,
                           const float* __restrict__ w_m, const float* __restrict__ b_m,
                           const float* __restrict__ g_m, const float* __restrict__ be_m,
                           const float* __restrict__ w_l, const float* __restrict__ b_l,
                           const float* __restrict__ g_l, const float* __restrict__ be_l,
                           float* __restrict__ out_s, float* __restrict__ out_m,
                           float* __restrict__ out_l) {
    __shared__ float red[16];
    const int token = blockIdx.x;
    const int t = token & (TQ - 1);
    const int d = threadIdx.x;

    float xr[32];
    #pragma unroll
    for (int j = 0; j < 32; j++)
        xr[j] = (t - j >= 0) ? emb[((size_t)(token - j)) * DQ + d] : 0.0f;

    float ys = b_s[d], ym = b_m[d], yl = b_l[d];
    #pragma unroll
    for (int j = 0; j < 2; j++)  ys += w_s[d * 2 + 1 - j] * xr[j];
    #pragma unroll
    for (int j = 0; j < 8; j++)  ym += w_m[d * 8 + 7 - j] * xr[j];
    #pragma unroll
    for (int j = 0; j < 32; j++) yl += w_l[d * 32 + 31 - j] * xr[j];

    const size_t base = (size_t)token * DQ + d;
    {
        float mu = block_sum_512(ys, red) * (1.0f / DQ);
        float dv = ys - mu;
        float var = block_sum_512(dv * dv, red) * (1.0f / DQ);
        out_s[base] = dv * rsqrtf(var + 1e-5f) * g_s[d] + be_s[d];
    }
    {
        float mu = block_sum_512(ym, red) * (1.0f / DQ);
        float dv = ym - mu;
        float var = block_sum_512(dv * dv, red) * (1.0f / DQ);
        out_m[base] = dv * rsqrtf(var + 1e-5f) * g_m[d] + be_m[d];
    }
    {
        float mu = block_sum_512(yl, red) * (1.0f / DQ);
        float dv = yl - mu;
        float var = block_sum_512(dv * dv, red) * (1.0f / DQ);
        out_l[base] = dv * rsqrtf(var + 1e-5f) * g_l[d] + be_l[d];
    }
}

// ============================================================================
// Tensor-core GEMM: C[M,N] = A[M,K] @ W[N,K]^T + bias (opt GELU), fp32 I/O.
// bf16 3-pass split (A=hi+lo, W=hi+lo; acc += AhWh + AhWl + AlWh).
// BM=BN=128, BK=32, 256 threads (8 warps: 4x2), warp tile 32x64.
// ============================================================================
struct GemmSmem {
    __nv_bfloat16 Ah[128][40];
    __nv_bfloat16 Al[128][40];
    __nv_bfloat16 Bh[128][40];
    __nv_bfloat16 Bl[128][40];
};

__device__ __forceinline__ void gemm_mainloop_k32(
    GemmSmem& sm, float acc[2][8][4], int warp_m, int warp_n, int lane) {
    #pragma unroll
    for (int ks = 0; ks < 32; ks += 16) {
        const int arow = (lane & 15);
        const int acol = ks + (lane >> 4) * 8;
        uint32_t ah[2][4], al[2][4];
        #pragma unroll
        for (int mi = 0; mi < 2; mi++) {
            int mb = warp_m * 32 + mi * 16;
            uint32_t addr_h = smem_u32(&sm.Ah[mb + arow][acol]);
            uint32_t addr_l = smem_u32(&sm.Al[mb + arow][acol]);
            LDSM4(ah[mi][0], ah[mi][1], ah[mi][2], ah[mi][3], addr_h);
            LDSM4(al[mi][0], al[mi][1], al[mi][2], al[mi][3], addr_l);
        }
        #pragma unroll
        for (int pair = 0; pair < 4; pair++) {
            int nb = warp_n * 64 + pair * 16;
            uint32_t bh[4], bl[4];
            uint32_t baddr_h = smem_u32(&sm.Bh[nb + arow][acol]);
            uint32_t baddr_l = smem_u32(&sm.Bl[nb + arow][acol]);
            LDSM4(bh[0], bh[1], bh[2], bh[3], baddr_h);
            LDSM4(bl[0], bl[1], bl[2], bl[3], baddr_l);
            uint32_t bEh[2] = {bh[0], bh[2]}, bOh[2] = {bh[1], bh[3]};
            uint32_t bEl[2] = {bl[0], bl[2]}, bOl[2] = {bl[1], bl[3]};
            #pragma unroll
            for (int mi = 0; mi < 2; mi++) {
                MMA16816(acc[mi][2 * pair],     ah[mi], bEh);
                MMA16816(acc[mi][2 * pair],     ah[mi], bEl);
                MMA16816(acc[mi][2 * pair],     al[mi], bEh);
                MMA16816(acc[mi][2 * pair + 1], ah[mi], bOh);
                MMA16816(acc[mi][2 * pair + 1], ah[mi], bOl);
                MMA16816(acc[mi][2 * pair + 1], al[mi], bOh);
            }
        }
    }
}

template <bool GELU>
__device__ __forceinline__ void gemm_epilogue(
    float acc[2][8][4], const float* __restrict__ bias, float* __restrict__ C,
    int N, int m0, int n0, int warp_m, int warp_n, int lane) {
    const int g = lane >> 2, tg = lane & 3;
    #pragma unroll
    for (int mi = 0; mi < 2; mi++) {
        #pragma unroll
        for (int ni = 0; ni < 8; ni++) {
            int row = m0 + warp_m * 32 + mi * 16 + g;
            int col = n0 + warp_n * 64 + ni * 8 + tg * 2;
            float b0 = bias[col], b1 = bias[col + 1];
            float v0 = acc[mi][ni][0] + b0, v1 = acc[mi][ni][1] + b1;
            float v2 = acc[mi][ni][2] + b0, v3 = acc[mi][ni][3] + b1;
            if (GELU) {
                v0 = gelu_exact(v0); v1 = gelu_exact(v1);
                v2 = gelu_exact(v2); v3 = gelu_exact(v3);
            }
            *reinterpret_cast<float2*>(&C[(size_t)row * N + col]) = make_float2(v0, v1);
            *reinterpret_cast<float2*>(&C[(size_t)(row + 8) * N + col]) = make_float2(v2, v3);
        }
    }
}

template <bool GELU>
__global__ __launch_bounds__(256)
void gemm_bf16_kernel(const float* __restrict__ A, const float* __restrict__ W,
                      const float* __restrict__ bias, float* __restrict__ C,
                      int M, int N, int K) {
    __shared__ GemmSmem sm;
    const int tid = threadIdx.x;
    const int lane = tid & 31, wid = tid >> 5;
    const int warp_m = wid >> 1, warp_n = wid & 1;
    const int m0 = blockIdx.y * 128, n0 = blockIdx.x * 128;

    float acc[2][8][4];
    #pragma unroll
    for (int mi = 0; mi < 2; mi++)
        #pragma unroll
        for (int ni = 0; ni < 8; ni++)
            #pragma unroll
            for (int j = 0; j < 4; j++) acc[mi][ni][j] = 0.0f;

    for (int k0 = 0; k0 < K; k0 += 32) {
        #pragma unroll
        for (int v = 0; v < 4; v++) {
            int f = v * 256 + tid;
            int r = f >> 3, c4 = (f & 7) << 2;
            float4 av = *reinterpret_cast<const float4*>(A + (size_t)(m0 + r) * K + k0 + c4);
            split4(av, &sm.Ah[r][c4], &sm.Al[r][c4]);
            float4 bv = *reinterpret_cast<const float4*>(W + (size_t)(n0 + r) * K + k0 + c4);
            split4(bv, &sm.Bh[r][c4], &sm.Bl[r][c4]);
        }
        __syncthreads();
        gemm_mainloop_k32(sm, acc, warp_m, warp_n, lane);
        __syncthreads();
    }
    gemm_epilogue<GELU>(acc, bias, C, N, m0, n0, warp_m, warp_n, lane);
}

// Segmented variant: logical A = concat of 512-wide segments (no copy buffer).
template <bool GELU, bool PREV>
__global__ __launch_bounds__(256)
void seg_gemm_bf16_kernel(SegPtrs segs, const float* __restrict__ W,
                          const float* __restrict__ bias, float* __restrict__ C,
                          int M, int N, int K) {
    __shared__ GemmSmem sm;
    const int tid = threadIdx.x;
    const int lane = tid & 31, wid = tid >> 5;
    const int warp_m = wid >> 1, warp_n = wid & 1;
    const int m0 = blockIdx.y * 128, n0 = blockIdx.x * 128;

    float acc[2][8][4];
    #pragma unroll
    for (int mi = 0; mi < 2; mi++)
        #pragma unroll
        for (int ni = 0; ni < 8; ni++)
            #pragma unroll
            for (int j = 0; j < 4; j++) acc[mi][ni][j] = 0.0f;

    for (int k0 = 0; k0 < K; k0 += 32) {
        const int seg = k0 >> 9;
        const int ks = k0 & 511;
        const float* __restrict__ Aseg = segs.p[seg];
        #pragma unroll
        for (int v = 0; v < 4; v++) {
            int f = v * 256 + tid;
            int r = f >> 3, c4 = (f & 7) << 2;
            int m = m0 + r;
            if (PREV && seg == 1) m = ((m & (TQ - 1)) == 0) ? m : m - 1;
            float4 av = *reinterpret_cast<const float4*>(Aseg + (size_t)m * DQ + ks + c4);
            split4(av, &sm.Ah[r][c4], &sm.Al[r][c4]);
            float4 bv = *reinterpret_cast<const float4*>(W + (size_t)(n0 + r) * K + k0 + c4);
            split4(bv, &sm.Bh[r][c4], &sm.Bl[r][c4]);
        }
        __syncthreads();
        gemm_mainloop_k32(sm, acc, warp_m, warp_n, lane);
        __syncthreads();
    }
    gemm_epilogue<GELU>(acc, bias, C, N, m0, n0, warp_m, warp_n, lane);
}

// ---------------- GRU persistent kernel ----------------
// 128 CTAs x 256 threads; CTA owns 4 state dims; W_hh slice in registers.
// Grid barrier: two-level tree (16 groups of 8 -> root), single-word sense poll.
__global__ void __launch_bounds__(256)
gru_kernel(const float* __restrict__ xg, const float* __restrict__ W_hh,
           const float* __restrict__ b_hh, float* __restrict__ memc) {
    __shared__ float h_sh[BQ * DQ];
    __shared__ float hg_sh[BQ * 12];

    const int tid = threadIdx.x;
    const int w = tid >> 5, lane = tid & 31;
    const int bp = w & 1, rh = w >> 1;
    const int d0 = blockIdx.x * 4;

    unsigned long long wreg[3][8];
    #pragma unroll
    for (int rl = 0; rl < 3; rl++) {
        int lr = rh * 3 + rl;
        int grow = (lr >> 2) * DQ + d0 + (lr & 3);
        const float* wp = W_hh + (size_t)grow * DQ;
        #pragma unroll
        for (int j = 0; j < 8; j++) {
            float2 v = *reinterpret_cast<const float2*>(wp + j * 64 + lane * 2);
            wreg[rl][j] = pack2(v.x, v.y);
        }
    }

    for (int t = 0; t < TQ; t++) {
        const float* hin = g_hbuf[t & 1];
        float* hout = g_hbuf[(t + 1) & 1];

        const float4* hp = reinterpret_cast<const float4*>(hin);
        #pragma unroll
        for (int v = 0; v < 4; v++)
            reinterpret_cast<float4*>(h_sh)[tid + v * 256] = hp[tid + v * 256];

        float xr = 0.f, xz = 0.f, xn = 0.f;
        if (tid < 32) {
            int b = tid >> 2, i = tid & 3;
            size_t base = ((size_t)(b * TQ + t)) * (3 * DQ) + d0 + i;
            xr = xg[base];
            xz = xg[base + DQ];
            xn = xg[base + 2 * DQ];
        }
        __syncthreads();

        unsigned long long acc[3][4];
        #pragma unroll
        for (int rl = 0; rl < 3; rl++)
            #pragma unroll
            for (int bb = 0; bb < 4; bb++) acc[rl][bb] = 0ull;

        #pragma unroll
        for (int j = 0; j < 8; j++) {
            unsigned long long h2[4];
            #pragma unroll
            for (int bb = 0; bb < 4; bb++)
                h2[bb] = *reinterpret_cast<const unsigned long long*>(
                    &h_sh[(bp * 4 + bb) * DQ + j * 64 + lane * 2]);
            #pragma unroll
            for (int rl = 0; rl < 3; rl++)
                #pragma unroll
                for (int bb = 0; bb < 4; bb++)
                    FMA2(acc[rl][bb], h2[bb], wreg[rl][j]);
        }

        #pragma unroll
        for (int rl = 0; rl < 3; rl++)
            #pragma unroll
            for (int bb = 0; bb < 4; bb++) {
                float x, y;
                unpack2(acc[rl][bb], x, y);
                float s = x + y;
                #pragma unroll
                for (int off = 16; off > 0; off >>= 1)
                    s += __shfl_xor_sync(0xffffffffu, s, off);
                if (lane == 0) hg_sh[(bp * 4 + bb) * 12 + rh * 3 + rl] = s;
            }
        __syncthreads();

        if (tid < 32) {
            int b = tid >> 2, i = tid & 3;
            int d = d0 + i;
            float hr = hg_sh[b * 12 + i]     + b_hh[d];
            float hz = hg_sh[b * 12 + 4 + i] + b_hh[DQ + d];
            float hn = hg_sh[b * 12 + 8 + i] + b_hh[2 * DQ + d];
            float r = 1.0f / (1.0f + expf(-(xr + hr)));
            float z = 1.0f / (1.0f + expf(-(xz + hz)));
            float n = tanhf(xn + r * hn);
            float hold = h_sh[b * DQ + d];
            float hnew = (1.0f - z) * n + z * hold;
            hout[b * DQ + d] = hnew;
            memc[((size_t)(b * TQ + t)) * DQ + d] = hnew;
        }
        __syncthreads();

        // two-level tree barrier: 8-way group atomics -> 16-way root -> sense
        if (tid == 0) {
            __threadfence();
            const unsigned step = (unsigned)(t + 1);
            const int g = blockIdx.x >> 3;
            unsigned a = atomicAdd(&g_grp[g], 1u) + 1u;
            if (a == step * 8u) {
                unsigned r = atomicAdd(&g_root, 1u) + 1u;
                if (r == step * 16u) {
                    g_sense = step;
                }
            }
            int spins = 0;
            while (g_sense < step) {
                if (++spins > 32) __nanosleep(32);
            }
            __threadfence();
        }
        __syncthreads();
    }
}

__global__ void reset_kernel() {
    int tid = threadIdx.x;
    for (int i = tid; i < BQ * DQ; i += blockDim.x) {
        g_hbuf[0][i] = 0.0f;
        g_hbuf[1][i] = 0.0f;
    }
    if (tid < 16) g_grp[tid] = 0u;
    if (tid == 0) { g_root = 0u; g_sense = 0u; }
}

// ---------------- final residual + LN ----------------
__global__ void final_kernel(const float* __restrict__ emb, const float* __restrict__ fused,
                             const float* __restrict__ change,
                             const float* __restrict__ ln_g, const float* __restrict__ ln_b,
                             float* __restrict__ out) {
    __shared__ float red[16];
    const int token = blockIdx.x;
    const int d = threadIdx.x;
    const size_t base = (size_t)token * DQ + d;
    float x = emb[base] + fused[base] + change[base];
    float mu = block_sum_512(x, red) * (1.0f / DQ);
    float dv = x - mu;
    float var = block_sum_512(dv * dv, red) * (1.0f / DQ);
    out[base] = dv * rsqrtf(var + 1e-5f) * ln_g[d] + ln_b[d];
}

// ---------------- launch ----------------
static float* symp(const void* sym) {
    void* p = nullptr;
    cudaGetSymbolAddress(&p, sym);
    return (float*)p;
}

extern "C" void kernel_launch(void* const* d_in, const int* in_sizes, int n_in,
                              void* d_out, int out_size) {
    const float* emb   = (const float*)d_in[0];
    const float* w_s   = (const float*)d_in[1];
    const float* b_s   = (const float*)d_in[2];
    const float* gs    = (const float*)d_in[3];
    const float* bes   = (const float*)d_in[4];
    const float* w_m   = (const float*)d_in[5];
    const float* b_m   = (const float*)d_in[6];
    const float* gm    = (const float*)d_in[7];
    const float* bem   = (const float*)d_in[8];
    const float* w_l   = (const float*)d_in[9];
    const float* b_l   = (const float*)d_in[10];
    const float* gl    = (const float*)d_in[11];
    const float* bel   = (const float*)d_in[12];
    const float* W_ih  = (const float*)d_in[13];
    const float* W_hh  = (const float*)d_in[14];
    const float* b_ih  = (const float*)d_in[15];
    const float* b_hh  = (const float*)d_in[16];
    const float* ce_w1 = (const float*)d_in[17];
    const float* ce_b1 = (const float*)d_in[18];
    const float* ce_w2 = (const float*)d_in[19];
    const float* ce_b2 = (const float*)d_in[20];
    const float* fu_w1 = (const float*)d_in[21];
    const float* fu_b1 = (const float*)d_in[22];
    const float* fu_w2 = (const float*)d_in[23];
    const float* fu_b2 = (const float*)d_in[24];
    const float* ln_g  = (const float*)d_in[25];
    const float* ln_b  = (const float*)d_in[26];

    float* sctx   = symp(g_short);
    float* mctx   = symp(g_mid);
    float* lctx   = symp(g_long);
    float* memc   = symp(g_memc);
    float* change = symp(g_change);
    float* fused  = symp(g_fused);
    float* xg     = symp(g_xg);
    float* h1     = symp(g_h1);
    float* fh     = symp(g_fh);

    // multi-scale conv + LN
    ctx_kernel<<<NTOK, 512>>>(emb, w_s, b_s, gs, bes, w_m, b_m, gm, bem,
                              w_l, b_l, gl, bel, sctx, mctx, lctx);

    // xg = emb @ W_ih^T + b_ih   (M=16384, N=1536, K=512)
    gemm_bf16_kernel<false><<<dim3(12, 128), 256>>>(emb, W_ih, b_ih, xg, NTOK, 1536, 512);

    // change path
    {
        SegPtrs sp{};
        sp.p[0] = emb; sp.p[1] = emb;
        seg_gemm_bf16_kernel<true, true><<<dim3(2, 128), 256>>>(sp, ce_w1, ce_b1, h1,
                                                                NTOK, 256, 1024);
    }
    gemm_bf16_kernel<false><<<dim3(4, 128), 256>>>(h1, ce_w2, ce_b2, change, NTOK, 512, 256);

    // GRU recurrence
    reset_kernel<<<1, 256>>>();
    gru_kernel<<<GRU_CTAS, 256>>>(xg, W_hh, b_hh, memc);

    // fusion path
    {
        SegPtrs sp{};
        sp.p[0] = emb; sp.p[1] = sctx; sp.p[2] = mctx; sp.p[3] = lctx; sp.p[4] = memc;
        seg_gemm_bf16_kernel<true, false><<<dim3(8, 128), 256>>>(sp, fu_w1, fu_b1, fh,
                                                                 NTOK, 1024, 2560);
    }
    gemm_bf16_kernel<false><<<dim3(4, 128), 256>>>(fh, fu_w2, fu_b2, fused, NTOK, 512, 1024);

    // out = LN(emb + fused + change)
    final_kernel<<<NTOK, 512>>>(emb, fused, change, ln_g, ln_b, (float*)d_out);
}

// round 8
// speedup vs baseline: 2.2207x; 1.2864x over previous
#include <cuda_runtime.h>
#include <cuda_bf16.h>
#include <math.h>
#include <stdint.h>

#define BQ 8
#define TQ 2048
#define DQ 512
#define NTOK (BQ * TQ)            // 16384
#define GRU_CTAS 128

// ---------------- scratch (device globals; allocation-free) ----------------
__device__ float g_short[NTOK * DQ];
__device__ float g_mid[NTOK * DQ];
__device__ float g_long[NTOK * DQ];
__device__ float g_memc[NTOK * DQ];
__device__ float g_change[NTOK * DQ];
__device__ float g_fused[NTOK * DQ];
__device__ float g_xg[NTOK * 3 * DQ];
__device__ float g_h1[NTOK * 256];
__device__ float g_fh[NTOK * 1024];
__device__ float g_hbuf[2][BQ * DQ];
__device__ unsigned g_grp[16];              // legacy tree barrier
__device__ unsigned g_root;
__device__ volatile unsigned g_sense;

struct SegPtrs { const float* p[5]; };

// ---------------- helpers ----------------
__device__ __forceinline__ float gelu_exact(float x) {
    return 0.5f * x * (1.0f + erff(x * 0.70710678118654752440f));
}

#define FMA2(d, a, b) asm("fma.rn.f32x2 %0, %1, %2, %0;" : "+l"(d) : "l"(a), "l"(b))

__device__ __forceinline__ unsigned long long pack2(float x, float y) {
    unsigned long long r;
    asm("mov.b64 %0, {%1, %2};" : "=l"(r) : "r"(__float_as_uint(x)), "r"(__float_as_uint(y)));
    return r;
}
__device__ __forceinline__ void unpack2(unsigned long long v, float& x, float& y) {
    unsigned lo, hi;
    asm("mov.b64 {%0, %1}, %2;" : "=r"(lo), "=r"(hi) : "l"(v));
    x = __uint_as_float(lo); y = __uint_as_float(hi);
}

__device__ __forceinline__ float block_sum_512(float v, float* red) {
    int lane = threadIdx.x & 31, w = threadIdx.x >> 5;
    #pragma unroll
    for (int off = 16; off > 0; off >>= 1) v += __shfl_xor_sync(0xffffffffu, v, off);
    if (lane == 0) red[w] = v;
    __syncthreads();
    float s = (threadIdx.x < 16) ? red[threadIdx.x] : 0.0f;
    if (w == 0) {
        #pragma unroll
        for (int off = 8; off > 0; off >>= 1) s += __shfl_xor_sync(0xffffffffu, s, off);
        if (lane == 0) red[0] = s;
    }
    __syncthreads();
    float r = red[0];
    __syncthreads();
    return r;
}

__device__ __forceinline__ uint32_t smem_u32(const void* p) {
    return (uint32_t)__cvta_generic_to_shared(p);
}

__device__ __forceinline__ uint32_t my_ctarank() {
    uint32_t r; asm("mov.u32 %0, %%cluster_ctarank;" : "=r"(r)); return r;
}

__device__ __forceinline__ void st_cluster_f32(uint32_t local_smem_addr, int peer, float v) {
    uint32_t remote;
    asm volatile("mapa.shared::cluster.u32 %0, %1, %2;"
                 : "=r"(remote) : "r"(local_smem_addr), "r"(peer));
    asm volatile("st.shared::cluster.f32 [%0], %1;" :: "r"(remote), "f"(v) : "memory");
}

#define CLUSTER_BARRIER_ARRIVE() \
    asm volatile("barrier.cluster.arrive.aligned;" ::: "memory")
#define CLUSTER_BARRIER_WAIT() \
    asm volatile("barrier.cluster.wait.aligned;" ::: "memory")

#define LDSM4(r0, r1, r2, r3, addr) \
    asm volatile("ldmatrix.sync.aligned.m8n8.x4.shared.b16 {%0,%1,%2,%3},[%4];" \
                 : "=r"(r0), "=r"(r1), "=r"(r2), "=r"(r3) : "r"(addr))

#define MMA16816(d, a, b) \
    asm volatile("mma.sync.aligned.m16n8k16.row.col.f32.bf16.bf16.f32 " \
                 "{%0,%1,%2,%3},{%4,%5,%6,%7},{%8,%9},{%0,%1,%2,%3};" \
                 : "+f"((d)[0]), "+f"((d)[1]), "+f"((d)[2]), "+f"((d)[3]) \
                 : "r"((a)[0]), "r"((a)[1]), "r"((a)[2]), "r"((a)[3]), \
                   "r"((b)[0]), "r"((b)[1]))

__device__ __forceinline__ void split4(float4 v, __nv_bfloat16* hi, __nv_bfloat16* lo) {
    float x[4] = {v.x, v.y, v.z, v.w};
    #pragma unroll
    for (int i = 0; i < 4; i++) {
        __nv_bfloat16 h = __float2bfloat16(x[i]);
        hi[i] = h;
        lo[i] = __float2bfloat16(x[i] - __bfloat162float(h));
    }
}

// ---------------- conv (3 scales) + per-scale LN, fused ----------------
__global__ void ctx_kernel(const float* __restrict__ emb,
                           const float* __restrict__ w_s, const float* __restrict__ b_s,
                           const float* __restrict__ g_s, const float* __restrict__ be_s,
                           const float* __restrict__ w_m, const float* __restrict__ b_m,
                           const float* __restrict__ g_m, const float* __restrict__ be_m,
                           const float* __restrict__ w_l, const float* __restrict__ b_l,
                           const float* __restrict__ g_l, const float* __restrict__ be_l,
                           float* __restrict__ out_s, float* __restrict__ out_m,
                           float* __restrict__ out_l) {
    __shared__ float red[16];
    const int token = blockIdx.x;
    const int t = token & (TQ - 1);
    const int d = threadIdx.x;

    float xr[32];
    #pragma unroll
    for (int j = 0; j < 32; j++)
        xr[j] = (t - j >= 0) ? emb[((size_t)(token - j)) * DQ + d] : 0.0f;

    float ys = b_s[d], ym = b_m[d], yl = b_l[d];
    #pragma unroll
    for (int j = 0; j < 2; j++)  ys += w_s[d * 2 + 1 - j] * xr[j];
    #pragma unroll
    for (int j = 0; j < 8; j++)  ym += w_m[d * 8 + 7 - j] * xr[j];
    #pragma unroll
    for (int j = 0; j < 32; j++) yl += w_l[d * 32 + 31 - j] * xr[j];

    const size_t base = (size_t)token * DQ + d;
    {
        float mu = block_sum_512(ys, red) * (1.0f / DQ);
        float dv = ys - mu;
        float var = block_sum_512(dv * dv, red) * (1.0f / DQ);
        out_s[base] = dv * rsqrtf(var + 1e-5f) * g_s[d] + be_s[d];
    }
    {
        float mu = block_sum_512(ym, red) * (1.0f / DQ);
        float dv = ym - mu;
        float var = block_sum_512(dv * dv, red) * (1.0f / DQ);
        out_m[base] = dv * rsqrtf(var + 1e-5f) * g_m[d] + be_m[d];
    }
    {
        float mu = block_sum_512(yl, red) * (1.0f / DQ);
        float dv = yl - mu;
        float var = block_sum_512(dv * dv, red) * (1.0f / DQ);
        out_l[base] = dv * rsqrtf(var + 1e-5f) * g_l[d] + be_l[d];
    }
}

// ============================================================================
// Tensor-core GEMM (unchanged from R7)
// ============================================================================
struct GemmSmem {
    __nv_bfloat16 Ah[128][40];
    __nv_bfloat16 Al[128][40];
    __nv_bfloat16 Bh[128][40];
    __nv_bfloat16 Bl[128][40];
};

__device__ __forceinline__ void gemm_mainloop_k32(
    GemmSmem& sm, float acc[2][8][4], int warp_m, int warp_n, int lane) {
    #pragma unroll
    for (int ks = 0; ks < 32; ks += 16) {
        const int arow = (lane & 15);
        const int acol = ks + (lane >> 4) * 8;
        uint32_t ah[2][4], al[2][4];
        #pragma unroll
        for (int mi = 0; mi < 2; mi++) {
            int mb = warp_m * 32 + mi * 16;
            uint32_t addr_h = smem_u32(&sm.Ah[mb + arow][acol]);
            uint32_t addr_l = smem_u32(&sm.Al[mb + arow][acol]);
            LDSM4(ah[mi][0], ah[mi][1], ah[mi][2], ah[mi][3], addr_h);
            LDSM4(al[mi][0], al[mi][1], al[mi][2], al[mi][3], addr_l);
        }
        #pragma unroll
        for (int pair = 0; pair < 4; pair++) {
            int nb = warp_n * 64 + pair * 16;
            uint32_t bh[4], bl[4];
            uint32_t baddr_h = smem_u32(&sm.Bh[nb + arow][acol]);
            uint32_t baddr_l = smem_u32(&sm.Bl[nb + arow][acol]);
            LDSM4(bh[0], bh[1], bh[2], bh[3], baddr_h);
            LDSM4(bl[0], bl[1], bl[2], bl[3], baddr_l);
            uint32_t bEh[2] = {bh[0], bh[2]}, bOh[2] = {bh[1], bh[3]};
            uint32_t bEl[2] = {bl[0], bl[2]}, bOl[2] = {bl[1], bl[3]};
            #pragma unroll
            for (int mi = 0; mi < 2; mi++) {
                MMA16816(acc[mi][2 * pair],     ah[mi], bEh);
                MMA16816(acc[mi][2 * pair],     ah[mi], bEl);
                MMA16816(acc[mi][2 * pair],     al[mi], bEh);
                MMA16816(acc[mi][2 * pair + 1], ah[mi], bOh);
                MMA16816(acc[mi][2 * pair + 1], ah[mi], bOl);
                MMA16816(acc[mi][2 * pair + 1], al[mi], bOh);
            }
        }
    }
}

template <bool GELU>
__device__ __forceinline__ void gemm_epilogue(
    float acc[2][8][4], const float* __restrict__ bias, float* __restrict__ C,
    int N, int m0, int n0, int warp_m, int warp_n, int lane) {
    const int g = lane >> 2, tg = lane & 3;
    #pragma unroll
    for (int mi = 0; mi < 2; mi++) {
        #pragma unroll
        for (int ni = 0; ni < 8; ni++) {
            int row = m0 + warp_m * 32 + mi * 16 + g;
            int col = n0 + warp_n * 64 + ni * 8 + tg * 2;
            float b0 = bias[col], b1 = bias[col + 1];
            float v0 = acc[mi][ni][0] + b0, v1 = acc[mi][ni][1] + b1;
            float v2 = acc[mi][ni][2] + b0, v3 = acc[mi][ni][3] + b1;
            if (GELU) {
                v0 = gelu_exact(v0); v1 = gelu_exact(v1);
                v2 = gelu_exact(v2); v3 = gelu_exact(v3);
            }
            *reinterpret_cast<float2*>(&C[(size_t)row * N + col]) = make_float2(v0, v1);
            *reinterpret_cast<float2*>(&C[(size_t)(row + 8) * N + col]) = make_float2(v2, v3);
        }
    }
}

template <bool GELU>
__global__ __launch_bounds__(256)
void gemm_bf16_kernel(const float* __restrict__ A, const float* __restrict__ W,
                      const float* __restrict__ bias, float* __restrict__ C,
                      int M, int N, int K) {
    __shared__ GemmSmem sm;
    const int tid = threadIdx.x;
    const int lane = tid & 31, wid = tid >> 5;
    const int warp_m = wid >> 1, warp_n = wid & 1;
    const int m0 = blockIdx.y * 128, n0 = blockIdx.x * 128;

    float acc[2][8][4];
    #pragma unroll
    for (int mi = 0; mi < 2; mi++)
        #pragma unroll
        for (int ni = 0; ni < 8; ni++)
            #pragma unroll
            for (int j = 0; j < 4; j++) acc[mi][ni][j] = 0.0f;

    for (int k0 = 0; k0 < K; k0 += 32) {
        #pragma unroll
        for (int v = 0; v < 4; v++) {
            int f = v * 256 + tid;
            int r = f >> 3, c4 = (f & 7) << 2;
            float4 av = *reinterpret_cast<const float4*>(A + (size_t)(m0 + r) * K + k0 + c4);
            split4(av, &sm.Ah[r][c4], &sm.Al[r][c4]);
            float4 bv = *reinterpret_cast<const float4*>(W + (size_t)(n0 + r) * K + k0 + c4);
            split4(bv, &sm.Bh[r][c4], &sm.Bl[r][c4]);
        }
        __syncthreads();
        gemm_mainloop_k32(sm, acc, warp_m, warp_n, lane);
        __syncthreads();
    }
    gemm_epilogue<GELU>(acc, bias, C, N, m0, n0, warp_m, warp_n, lane);
}

template <bool GELU, bool PREV>
__global__ __launch_bounds__(256)
void seg_gemm_bf16_kernel(SegPtrs segs, const float* __restrict__ W,
                          const float* __restrict__ bias, float* __restrict__ C,
                          int M, int N, int K) {
    __shared__ GemmSmem sm;
    const int tid = threadIdx.x;
    const int lane = tid & 31, wid = tid >> 5;
    const int warp_m = wid >> 1, warp_n = wid & 1;
    const int m0 = blockIdx.y * 128, n0 = blockIdx.x * 128;

    float acc[2][8][4];
    #pragma unroll
    for (int mi = 0; mi < 2; mi++)
        #pragma unroll
        for (int ni = 0; ni < 8; ni++)
            #pragma unroll
            for (int j = 0; j < 4; j++) acc[mi][ni][j] = 0.0f;

    for (int k0 = 0; k0 < K; k0 += 32) {
        const int seg = k0 >> 9;
        const int ks = k0 & 511;
        const float* __restrict__ Aseg = segs.p[seg];
        #pragma unroll
        for (int v = 0; v < 4; v++) {
            int f = v * 256 + tid;
            int r = f >> 3, c4 = (f & 7) << 2;
            int m = m0 + r;
            if (PREV && seg == 1) m = ((m & (TQ - 1)) == 0) ? m : m - 1;
            float4 av = *reinterpret_cast<const float4*>(Aseg + (size_t)m * DQ + ks + c4);
            split4(av, &sm.Ah[r][c4], &sm.Al[r][c4]);
            float4 bv = *reinterpret_cast<const float4*>(W + (size_t)(n0 + r) * K + k0 + c4);
            split4(bv, &sm.Bh[r][c4], &sm.Bl[r][c4]);
        }
        __syncthreads();
        gemm_mainloop_k32(sm, acc, warp_m, warp_n, lane);
        __syncthreads();
    }
    gemm_epilogue<GELU>(acc, bias, C, N, m0, n0, warp_m, warp_n, lane);
}

// ============================================================================
// GRU — cluster version: 8 clusters x 16 CTAs x 256 thr, one batch/cluster.
// CTA rank owns 32 h-dims (96 W_hh rows in 96 f32x2 regs). h exchanged via
// DSMEM (st.shared::cluster), double-buffered; split cluster arrive/wait.
// No global atomics, no L2 in the recurrence loop.
// ============================================================================
__global__ void __launch_bounds__(256, 1)
gru_cluster_kernel(const float* __restrict__ xg, const float* __restrict__ W_hh,
                   const float* __restrict__ b_hh, float* __restrict__ memc) {
    __shared__ float hbuf[2][DQ];
    __shared__ float hg_sh[96];
    __shared__ float xg_sh[96];

    const int tid = threadIdx.x;
    const int w = tid >> 5, lane = tid & 31;
    const int rank = (int)my_ctarank();
    const int batch = blockIdx.x >> 4;
    const int d0 = rank * 32;

    // weights: warp w handles rows rr = w*12 .. w*12+11 (row = gate*32 + dim)
    unsigned long long wreg[12][8];
    #pragma unroll
    for (int rl = 0; rl < 12; rl++) {
        int rr = w * 12 + rl;
        int g = rr >> 5, di = rr & 31;
        const float* wp = W_hh + (size_t)(g * DQ + d0 + di) * DQ;
        #pragma unroll
        for (int j = 0; j < 8; j++) {
            float2 v = *reinterpret_cast<const float2*>(wp + j * 64 + lane * 2);
            wreg[rl][j] = pack2(v.x, v.y);
        }
    }

    // biases for gate threads
    float bh_r = 0.f, bh_z = 0.f, bh_n = 0.f;
    if (tid < 32) {
        bh_r = b_hh[d0 + tid];
        bh_z = b_hh[DQ + d0 + tid];
        bh_n = b_hh[2 * DQ + d0 + tid];
    }

    // h_0 = 0
    hbuf[0][tid] = 0.f;
    hbuf[0][tid + 256] = 0.f;
    __syncthreads();
    CLUSTER_BARRIER_ARRIVE();
    CLUSTER_BARRIER_WAIT();

    for (int t = 0; t < TQ; t++) {
        // prefetch xg (independent of h) to overlap the cluster wait
        float xv = 0.f;
        if (tid < 96) {
            int g = tid >> 5, i = tid & 31;
            xv = xg[(size_t)(batch * TQ + t) * (3 * DQ) + g * DQ + d0 + i];
        }
        if (t > 0) CLUSTER_BARRIER_WAIT();

        const float* hcur = hbuf[t & 1];
        unsigned long long acc[12];
        #pragma unroll
        for (int rl = 0; rl < 12; rl++) acc[rl] = 0ull;
        #pragma unroll
        for (int j = 0; j < 8; j++) {
            unsigned long long h2 =
                *reinterpret_cast<const unsigned long long*>(&hcur[j * 64 + lane * 2]);
            #pragma unroll
            for (int rl = 0; rl < 12; rl++) FMA2(acc[rl], h2, wreg[rl][j]);
        }
        #pragma unroll
        for (int rl = 0; rl < 12; rl++) {
            float x, y;
            unpack2(acc[rl], x, y);
            float s = x + y;
            #pragma unroll
            for (int off = 16; off > 0; off >>= 1)
                s += __shfl_xor_sync(0xffffffffu, s, off);
            if (lane == 0) hg_sh[w * 12 + rl] = s;
        }
        if (tid < 96) xg_sh[tid] = xv;
        __syncthreads();

        if (tid < 32) {
            float hr = hg_sh[tid] + bh_r;
            float hz = hg_sh[32 + tid] + bh_z;
            float hn = hg_sh[64 + tid] + bh_n;
            float r = 1.0f / (1.0f + expf(-(xg_sh[tid] + hr)));
            float z = 1.0f / (1.0f + expf(-(xg_sh[32 + tid] + hz)));
            float n = tanhf(xg_sh[64 + tid] + r * hn);
            float hold = hcur[d0 + tid];
            float hnew = (1.0f - z) * n + z * hold;
            uint32_t dst = smem_u32(&hbuf[(t + 1) & 1][d0 + tid]);
            #pragma unroll
            for (int p = 0; p < 16; p++) st_cluster_f32(dst, p, hnew);
            memc[(size_t)(batch * TQ + t) * DQ + d0 + tid] = hnew;
        }
        CLUSTER_BARRIER_ARRIVE();
    }
    CLUSTER_BARRIER_WAIT();
}

// ---------------- legacy GRU (fallback; R7, tree barrier) ----------------
__global__ void __launch_bounds__(256)
gru_kernel(const float* __restrict__ xg, const float* __restrict__ W_hh,
           const float* __restrict__ b_hh, float* __restrict__ memc) {
    __shared__ float h_sh[BQ * DQ];
    __shared__ float hg_sh[BQ * 12];

    const int tid = threadIdx.x;
    const int w = tid >> 5, lane = tid & 31;
    const int bp = w & 1, rh = w >> 1;
    const int d0 = blockIdx.x * 4;

    unsigned long long wreg[3][8];
    #pragma unroll
    for (int rl = 0; rl < 3; rl++) {
        int lr = rh * 3 + rl;
        int grow = (lr >> 2) * DQ + d0 + (lr & 3);
        const float* wp = W_hh + (size_t)grow * DQ;
        #pragma unroll
        for (int j = 0; j < 8; j++) {
            float2 v = *reinterpret_cast<const float2*>(wp + j * 64 + lane * 2);
            wreg[rl][j] = pack2(v.x, v.y);
        }
    }

    for (int t = 0; t < TQ; t++) {
        const float* hin = g_hbuf[t & 1];
        float* hout = g_hbuf[(t + 1) & 1];

        const float4* hp = reinterpret_cast<const float4*>(hin);
        #pragma unroll
        for (int v = 0; v < 4; v++)
            reinterpret_cast<float4*>(h_sh)[tid + v * 256] = hp[tid + v * 256];

        float xr = 0.f, xz = 0.f, xn = 0.f;
        if (tid < 32) {
            int b = tid >> 2, i = tid & 3;
            size_t base = ((size_t)(b * TQ + t)) * (3 * DQ) + d0 + i;
            xr = xg[base];
            xz = xg[base + DQ];
            xn = xg[base + 2 * DQ];
        }
        __syncthreads();

        unsigned long long acc[3][4];
        #pragma unroll
        for (int rl = 0; rl < 3; rl++)
            #pragma unroll
            for (int bb = 0; bb < 4; bb++) acc[rl][bb] = 0ull;

        #pragma unroll
        for (int j = 0; j < 8; j++) {
            unsigned long long h2[4];
            #pragma unroll
            for (int bb = 0; bb < 4; bb++)
                h2[bb] = *reinterpret_cast<const unsigned long long*>(
                    &h_sh[(bp * 4 + bb) * DQ + j * 64 + lane * 2]);
            #pragma unroll
            for (int rl = 0; rl < 3; rl++)
                #pragma unroll
                for (int bb = 0; bb < 4; bb++)
                    FMA2(acc[rl][bb], h2[bb], wreg[rl][j]);
        }

        #pragma unroll
        for (int rl = 0; rl < 3; rl++)
            #pragma unroll
            for (int bb = 0; bb < 4; bb++) {
                float x, y;
                unpack2(acc[rl][bb], x, y);
                float s = x + y;
                #pragma unroll
                for (int off = 16; off > 0; off >>= 1)
                    s += __shfl_xor_sync(0xffffffffu, s, off);
                if (lane == 0) hg_sh[(bp * 4 + bb) * 12 + rh * 3 + rl] = s;
            }
        __syncthreads();

        if (tid < 32) {
            int b = tid >> 2, i = tid & 3;
            int d = d0 + i;
            float hr = hg_sh[b * 12 + i]     + b_hh[d];
            float hz = hg_sh[b * 12 + 4 + i] + b_hh[DQ + d];
            float hn = hg_sh[b * 12 + 8 + i] + b_hh[2 * DQ + d];
            float r = 1.0f / (1.0f + expf(-(xr + hr)));
            float z = 1.0f / (1.0f + expf(-(xz + hz)));
            float n = tanhf(xn + r * hn);
            float hold = h_sh[b * DQ + d];
            float hnew = (1.0f - z) * n + z * hold;
            hout[b * DQ + d] = hnew;
            memc[((size_t)(b * TQ + t)) * DQ + d] = hnew;
        }
        __syncthreads();

        if (tid == 0) {
            __threadfence();
            const unsigned step = (unsigned)(t + 1);
            const int g = blockIdx.x >> 3;
            unsigned a = atomicAdd(&g_grp[g], 1u) + 1u;
            if (a == step * 8u) {
                unsigned r = atomicAdd(&g_root, 1u) + 1u;
                if (r == step * 16u) {
                    g_sense = step;
                }
            }
            int spins = 0;
            while (g_sense < step) {
                if (++spins > 32) __nanosleep(32);
            }
            __threadfence();
        }
        __syncthreads();
    }
}

__global__ void reset_kernel() {
    int tid = threadIdx.x;
    for (int i = tid; i < BQ * DQ; i += blockDim.x) {
        g_hbuf[0][i] = 0.0f;
        g_hbuf[1][i] = 0.0f;
    }
    if (tid < 16) g_grp[tid] = 0u;
    if (tid == 0) { g_root = 0u; g_sense = 0u; }
}

// ---------------- final residual + LN ----------------
__global__ void final_kernel(const float* __restrict__ emb, const float* __restrict__ fused,
                             const float* __restrict__ change,
                             const float* __restrict__ ln_g, const float* __restrict__ ln_b,
                             float* __restrict__ out) {
    __shared__ float red[16];
    const int token = blockIdx.x;
    const int d = threadIdx.x;
    const size_t base = (size_t)token * DQ + d;
    float x = emb[base] + fused[base] + change[base];
    float mu = block_sum_512(x, red) * (1.0f / DQ);
    float dv = x - mu;
    float var = block_sum_512(dv * dv, red) * (1.0f / DQ);
    out[base] = dv * rsqrtf(var + 1e-5f) * ln_g[d] + ln_b[d];
}

// ---------------- launch ----------------
static float* symp(const void* sym) {
    void* p = nullptr;
    cudaGetSymbolAddress(&p, sym);
    return (float*)p;
}

extern "C" void kernel_launch(void* const* d_in, const int* in_sizes, int n_in,
                              void* d_out, int out_size) {
    const float* emb   = (const float*)d_in[0];
    const float* w_s   = (const float*)d_in[1];
    const float* b_s   = (const float*)d_in[2];
    const float* gs    = (const float*)d_in[3];
    const float* bes   = (const float*)d_in[4];
    const float* w_m   = (const float*)d_in[5];
    const float* b_m   = (const float*)d_in[6];
    const float* gm    = (const float*)d_in[7];
    const float* bem   = (const float*)d_in[8];
    const float* w_l   = (const float*)d_in[9];
    const float* b_l   = (const float*)d_in[10];
    const float* gl    = (const float*)d_in[11];
    const float* bel   = (const float*)d_in[12];
    const float* W_ih  = (const float*)d_in[13];
    const float* W_hh  = (const float*)d_in[14];
    const float* b_ih  = (const float*)d_in[15];
    const float* b_hh  = (const float*)d_in[16];
    const float* ce_w1 = (const float*)d_in[17];
    const float* ce_b1 = (const float*)d_in[18];
    const float* ce_w2 = (const float*)d_in[19];
    const float* ce_b2 = (const float*)d_in[20];
    const float* fu_w1 = (const float*)d_in[21];
    const float* fu_b1 = (const float*)d_in[22];
    const float* fu_w2 = (const float*)d_in[23];
    const float* fu_b2 = (const float*)d_in[24];
    const float* ln_g  = (const float*)d_in[25];
    const float* ln_b  = (const float*)d_in[26];

    float* sctx   = symp(g_short);
    float* mctx   = symp(g_mid);
    float* lctx   = symp(g_long);
    float* memc   = symp(g_memc);
    float* change = symp(g_change);
    float* fused  = symp(g_fused);
    float* xg     = symp(g_xg);
    float* h1     = symp(g_h1);
    float* fh     = symp(g_fh);

    // multi-scale conv + LN
    ctx_kernel<<<NTOK, 512>>>(emb, w_s, b_s, gs, bes, w_m, b_m, gm, bem,
                              w_l, b_l, gl, bel, sctx, mctx, lctx);

    // xg = emb @ W_ih^T + b_ih
    gemm_bf16_kernel<false><<<dim3(12, 128), 256>>>(emb, W_ih, b_ih, xg, NTOK, 1536, 512);

    // change path
    {
        SegPtrs sp{};
        sp.p[0] = emb; sp.p[1] = emb;
        seg_gemm_bf16_kernel<true, true><<<dim3(2, 128), 256>>>(sp, ce_w1, ce_b1, h1,
                                                                NTOK, 256, 1024);
    }
    gemm_bf16_kernel<false><<<dim3(4, 128), 256>>>(h1, ce_w2, ce_b2, change, NTOK, 512, 256);

    // GRU recurrence: cluster path if 16-CTA clusters supported, else legacy.
    reset_kernel<<<1, 256>>>();
    {
        cudaFuncSetAttribute(gru_cluster_kernel,
                             cudaFuncAttributeNonPortableClusterSizeAllowed, 1);
        cudaLaunchConfig_t cfg = {};
        cfg.gridDim = dim3(GRU_CTAS, 1, 1);
        cfg.blockDim = dim3(256, 1, 1);
        cfg.dynamicSmemBytes = 0;
        cfg.stream = 0;
        cudaLaunchAttribute attrs[1];
        attrs[0].id = cudaLaunchAttributeClusterDimension;
        attrs[0].val.clusterDim.x = 16;
        attrs[0].val.clusterDim.y = 1;
        attrs[0].val.clusterDim.z = 1;
        cfg.attrs = attrs;
        cfg.numAttrs = 1;

        int nclust = 0;
        cudaError_t qe = cudaOccupancyMaxActiveClusters(&nclust, gru_cluster_kernel, &cfg);
        if (qe != cudaSuccess) { (void)cudaGetLastError(); nclust = 0; }

        if (nclust >= 1) {
            cudaLaunchKernelEx(&cfg, gru_cluster_kernel, xg, W_hh, b_hh, memc);
        } else {
            gru_kernel<<<GRU_CTAS, 256>>>(xg, W_hh, b_hh, memc);
        }
    }

    // fusion path
    {
        SegPtrs sp{};
        sp.p[0] = emb; sp.p[1] = sctx; sp.p[2] = mctx; sp.p[3] = lctx; sp.p[4] = memc;
        seg_gemm_bf16_kernel<true, false><<<dim3(8, 128), 256>>>(sp, fu_w1, fu_b1, fh,
                                                                 NTOK, 1024, 2560);
    }
    gemm_bf16_kernel<false><<<dim3(4, 128), 256>>>(fh, fu_w2, fu_b2, fused, NTOK, 512, 1024);

    // out = LN(emb + fused + change)
    final_kernel<<<NTOK, 512>>>(emb, fused, change, ln_g, ln_b, (float*)d_out);
}

// round 9
// speedup vs baseline: 2.3544x; 1.0602x over previous
#include <cuda_runtime.h>
#include <cuda_bf16.h>
#include <math.h>
#include <stdint.h>

#define BQ 8
#define TQ 2048
#define DQ 512
#define NTOK (BQ * TQ)            // 16384
#define GRU_CTAS 128

// ---------------- scratch (device globals; allocation-free) ----------------
__device__ float g_short[NTOK * DQ];
__device__ float g_mid[NTOK * DQ];
__device__ float g_long[NTOK * DQ];
__device__ float g_memc[NTOK * DQ];
__device__ float g_change[NTOK * DQ];
__device__ float g_fused[NTOK * DQ];
__device__ float g_xg[NTOK * 3 * DQ];
__device__ float g_h1[NTOK * 256];
__device__ float g_fh[NTOK * 1024];
__device__ float g_hbuf[2][BQ * DQ];
__device__ unsigned g_grp[16];              // legacy tree barrier
__device__ unsigned g_root;
__device__ volatile unsigned g_sense;

struct SegPtrs { const float* p[5]; };

// ---------------- helpers ----------------
__device__ __forceinline__ float gelu_exact(float x) {
    return 0.5f * x * (1.0f + erff(x * 0.70710678118654752440f));
}

#define FMA2(d, a, b) asm("fma.rn.f32x2 %0, %1, %2, %0;" : "+l"(d) : "l"(a), "l"(b))

__device__ __forceinline__ unsigned long long pack2(float x, float y) {
    unsigned long long r;
    asm("mov.b64 %0, {%1, %2};" : "=l"(r) : "r"(__float_as_uint(x)), "r"(__float_as_uint(y)));
    return r;
}
__device__ __forceinline__ void unpack2(unsigned long long v, float& x, float& y) {
    unsigned lo, hi;
    asm("mov.b64 {%0, %1}, %2;" : "=r"(lo), "=r"(hi) : "l"(v));
    x = __uint_as_float(lo); y = __uint_as_float(hi);
}

__device__ __forceinline__ float block_sum_512(float v, float* red) {
    int lane = threadIdx.x & 31, w = threadIdx.x >> 5;
    #pragma unroll
    for (int off = 16; off > 0; off >>= 1) v += __shfl_xor_sync(0xffffffffu, v, off);
    if (lane == 0) red[w] = v;
    __syncthreads();
    float s = (threadIdx.x < 16) ? red[threadIdx.x] : 0.0f;
    if (w == 0) {
        #pragma unroll
        for (int off = 8; off > 0; off >>= 1) s += __shfl_xor_sync(0xffffffffu, s, off);
        if (lane == 0) red[0] = s;
    }
    __syncthreads();
    float r = red[0];
    __syncthreads();
    return r;
}

__device__ __forceinline__ uint32_t smem_u32(const void* p) {
    return (uint32_t)__cvta_generic_to_shared(p);
}

__device__ __forceinline__ uint32_t my_ctarank() {
    uint32_t r; asm("mov.u32 %0, %%cluster_ctarank;" : "=r"(r)); return r;
}

__device__ __forceinline__ void st_cluster_f32(uint32_t local_smem_addr, int peer, float v) {
    uint32_t remote;
    asm volatile("mapa.shared::cluster.u32 %0, %1, %2;"
                 : "=r"(remote) : "r"(local_smem_addr), "r"(peer));
    asm volatile("st.shared::cluster.f32 [%0], %1;" :: "r"(remote), "f"(v) : "memory");
}

#define CLUSTER_BARRIER_ARRIVE() \
    asm volatile("barrier.cluster.arrive.aligned;" ::: "memory")
#define CLUSTER_BARRIER_WAIT() \
    asm volatile("barrier.cluster.wait.aligned;" ::: "memory")

#define LDSM4(r0, r1, r2, r3, addr) \
    asm volatile("ldmatrix.sync.aligned.m8n8.x4.shared.b16 {%0,%1,%2,%3},[%4];" \
                 : "=r"(r0), "=r"(r1), "=r"(r2), "=r"(r3) : "r"(addr))

#define MMA16816(d, a, b) \
    asm volatile("mma.sync.aligned.m16n8k16.row.col.f32.bf16.bf16.f32 " \
                 "{%0,%1,%2,%3},{%4,%5,%6,%7},{%8,%9},{%0,%1,%2,%3};" \
                 : "+f"((d)[0]), "+f"((d)[1]), "+f"((d)[2]), "+f"((d)[3]) \
                 : "r"((a)[0]), "r"((a)[1]), "r"((a)[2]), "r"((a)[3]), \
                   "r"((b)[0]), "r"((b)[1]))

__device__ __forceinline__ void split4(float4 v, __nv_bfloat16* hi, __nv_bfloat16* lo) {
    float x[4] = {v.x, v.y, v.z, v.w};
    #pragma unroll
    for (int i = 0; i < 4; i++) {
        __nv_bfloat16 h = __float2bfloat16(x[i]);
        hi[i] = h;
        lo[i] = __float2bfloat16(x[i] - __bfloat162float(h));
    }
}

// fast sigmoid/tanh (2-ulp class; fine vs 1e-3 tolerance)
__device__ __forceinline__ float fast_sigmoid(float x) {
    return __fdividef(1.0f, 1.0f + __expf(-x));
}
__device__ __forceinline__ float fast_tanh(float x) {
    return 2.0f * __fdividef(1.0f, 1.0f + __expf(-2.0f * x)) - 1.0f;
}

// ---------------- conv (3 scales) + per-scale LN, fused ----------------
__global__ void ctx_kernel(const float* __restrict__ emb,
                           const float* __restrict__ w_s, const float* __restrict__ b_s,
                           const float* __restrict__ g_s, const float* __restrict__ be_s,
                           const float* __restrict__ w_m, const float* __restrict__ b_m,
                           const float* __restrict__ g_m, const float* __restrict__ be_m,
                           const float* __restrict__ w_l, const float* __restrict__ b_l,
                           const float* __restrict__ g_l, const float* __restrict__ be_l,
                           float* __restrict__ out_s, float* __restrict__ out_m,
                           float* __restrict__ out_l) {
    __shared__ float red[16];
    const int token = blockIdx.x;
    const int t = token & (TQ - 1);
    const int d = threadIdx.x;

    float xr[32];
    #pragma unroll
    for (int j = 0; j < 32; j++)
        xr[j] = (t - j >= 0) ? emb[((size_t)(token - j)) * DQ + d] : 0.0f;

    float ys = b_s[d], ym = b_m[d], yl = b_l[d];
    #pragma unroll
    for (int j = 0; j < 2; j++)  ys += w_s[d * 2 + 1 - j] * xr[j];
    #pragma unroll
    for (int j = 0; j < 8; j++)  ym += w_m[d * 8 + 7 - j] * xr[j];
    #pragma unroll
    for (int j = 0; j < 32; j++) yl += w_l[d * 32 + 31 - j] * xr[j];

    const size_t base = (size_t)token * DQ + d;
    {
        float mu = block_sum_512(ys, red) * (1.0f / DQ);
        float dv = ys - mu;
        float var = block_sum_512(dv * dv, red) * (1.0f / DQ);
        out_s[base] = dv * rsqrtf(var + 1e-5f) * g_s[d] + be_s[d];
    }
    {
        float mu = block_sum_512(ym, red) * (1.0f / DQ);
        float dv = ym - mu;
        float var = block_sum_512(dv * dv, red) * (1.0f / DQ);
        out_m[base] = dv * rsqrtf(var + 1e-5f) * g_m[d] + be_m[d];
    }
    {
        float mu = block_sum_512(yl, red) * (1.0f / DQ);
        float dv = yl - mu;
        float var = block_sum_512(dv * dv, red) * (1.0f / DQ);
        out_l[base] = dv * rsqrtf(var + 1e-5f) * g_l[d] + be_l[d];
    }
}

// ============================================================================
// Tensor-core GEMM (unchanged — known good)
// ============================================================================
struct GemmSmem {
    __nv_bfloat16 Ah[128][40];
    __nv_bfloat16 Al[128][40];
    __nv_bfloat16 Bh[128][40];
    __nv_bfloat16 Bl[128][40];
};

__device__ __forceinline__ void gemm_mainloop_k32(
    GemmSmem& sm, float acc[2][8][4], int warp_m, int warp_n, int lane) {
    #pragma unroll
    for (int ks = 0; ks < 32; ks += 16) {
        const int arow = (lane & 15);
        const int acol = ks + (lane >> 4) * 8;
        uint32_t ah[2][4], al[2][4];
        #pragma unroll
        for (int mi = 0; mi < 2; mi++) {
            int mb = warp_m * 32 + mi * 16;
            uint32_t addr_h = smem_u32(&sm.Ah[mb + arow][acol]);
            uint32_t addr_l = smem_u32(&sm.Al[mb + arow][acol]);
            LDSM4(ah[mi][0], ah[mi][1], ah[mi][2], ah[mi][3], addr_h);
            LDSM4(al[mi][0], al[mi][1], al[mi][2], al[mi][3], addr_l);
        }
        #pragma unroll
        for (int pair = 0; pair < 4; pair++) {
            int nb = warp_n * 64 + pair * 16;
            uint32_t bh[4], bl[4];
            uint32_t baddr_h = smem_u32(&sm.Bh[nb + arow][acol]);
            uint32_t baddr_l = smem_u32(&sm.Bl[nb + arow][acol]);
            LDSM4(bh[0], bh[1], bh[2], bh[3], baddr_h);
            LDSM4(bl[0], bl[1], bl[2], bl[3], baddr_l);
            uint32_t bEh[2] = {bh[0], bh[2]}, bOh[2] = {bh[1], bh[3]};
            uint32_t bEl[2] = {bl[0], bl[2]}, bOl[2] = {bl[1], bl[3]};
            #pragma unroll
            for (int mi = 0; mi < 2; mi++) {
                MMA16816(acc[mi][2 * pair],     ah[mi], bEh);
                MMA16816(acc[mi][2 * pair],     ah[mi], bEl);
                MMA16816(acc[mi][2 * pair],     al[mi], bEh);
                MMA16816(acc[mi][2 * pair + 1], ah[mi], bOh);
                MMA16816(acc[mi][2 * pair + 1], ah[mi], bOl);
                MMA16816(acc[mi][2 * pair + 1], al[mi], bOh);
            }
        }
    }
}

template <bool GELU>
__device__ __forceinline__ void gemm_epilogue(
    float acc[2][8][4], const float* __restrict__ bias, float* __restrict__ C,
    int N, int m0, int n0, int warp_m, int warp_n, int lane) {
    const int g = lane >> 2, tg = lane & 3;
    #pragma unroll
    for (int mi = 0; mi < 2; mi++) {
        #pragma unroll
        for (int ni = 0; ni < 8; ni++) {
            int row = m0 + warp_m * 32 + mi * 16 + g;
            int col = n0 + warp_n * 64 + ni * 8 + tg * 2;
            float b0 = bias[col], b1 = bias[col + 1];
            float v0 = acc[mi][ni][0] + b0, v1 = acc[mi][ni][1] + b1;
            float v2 = acc[mi][ni][2] + b0, v3 = acc[mi][ni][3] + b1;
            if (GELU) {
                v0 = gelu_exact(v0); v1 = gelu_exact(v1);
                v2 = gelu_exact(v2); v3 = gelu_exact(v3);
            }
            *reinterpret_cast<float2*>(&C[(size_t)row * N + col]) = make_float2(v0, v1);
            *reinterpret_cast<float2*>(&C[(size_t)(row + 8) * N + col]) = make_float2(v2, v3);
        }
    }
}

template <bool GELU>
__global__ __launch_bounds__(256)
void gemm_bf16_kernel(const float* __restrict__ A, const float* __restrict__ W,
                      const float* __restrict__ bias, float* __restrict__ C,
                      int M, int N, int K) {
    __shared__ GemmSmem sm;
    const int tid = threadIdx.x;
    const int lane = tid & 31, wid = tid >> 5;
    const int warp_m = wid >> 1, warp_n = wid & 1;
    const int m0 = blockIdx.y * 128, n0 = blockIdx.x * 128;

    float acc[2][8][4];
    #pragma unroll
    for (int mi = 0; mi < 2; mi++)
        #pragma unroll
        for (int ni = 0; ni < 8; ni++)
            #pragma unroll
            for (int j = 0; j < 4; j++) acc[mi][ni][j] = 0.0f;

    for (int k0 = 0; k0 < K; k0 += 32) {
        #pragma unroll
        for (int v = 0; v < 4; v++) {
            int f = v * 256 + tid;
            int r = f >> 3, c4 = (f & 7) << 2;
            float4 av = *reinterpret_cast<const float4*>(A + (size_t)(m0 + r) * K + k0 + c4);
            split4(av, &sm.Ah[r][c4], &sm.Al[r][c4]);
            float4 bv = *reinterpret_cast<const float4*>(W + (size_t)(n0 + r) * K + k0 + c4);
            split4(bv, &sm.Bh[r][c4], &sm.Bl[r][c4]);
        }
        __syncthreads();
        gemm_mainloop_k32(sm, acc, warp_m, warp_n, lane);
        __syncthreads();
    }
    gemm_epilogue<GELU>(acc, bias, C, N, m0, n0, warp_m, warp_n, lane);
}

template <bool GELU, bool PREV>
__global__ __launch_bounds__(256)
void seg_gemm_bf16_kernel(SegPtrs segs, const float* __restrict__ W,
                          const float* __restrict__ bias, float* __restrict__ C,
                          int M, int N, int K) {
    __shared__ GemmSmem sm;
    const int tid = threadIdx.x;
    const int lane = tid & 31, wid = tid >> 5;
    const int warp_m = wid >> 1, warp_n = wid & 1;
    const int m0 = blockIdx.y * 128, n0 = blockIdx.x * 128;

    float acc[2][8][4];
    #pragma unroll
    for (int mi = 0; mi < 2; mi++)
        #pragma unroll
        for (int ni = 0; ni < 8; ni++)
            #pragma unroll
            for (int j = 0; j < 4; j++) acc[mi][ni][j] = 0.0f;

    for (int k0 = 0; k0 < K; k0 += 32) {
        const int seg = k0 >> 9;
        const int ks = k0 & 511;
        const float* __restrict__ Aseg = segs.p[seg];
        #pragma unroll
        for (int v = 0; v < 4; v++) {
            int f = v * 256 + tid;
            int r = f >> 3, c4 = (f & 7) << 2;
            int m = m0 + r;
            if (PREV && seg == 1) m = ((m & (TQ - 1)) == 0) ? m : m - 1;
            float4 av = *reinterpret_cast<const float4*>(Aseg + (size_t)m * DQ + ks + c4);
            split4(av, &sm.Ah[r][c4], &sm.Al[r][c4]);
            float4 bv = *reinterpret_cast<const float4*>(W + (size_t)(n0 + r) * K + k0 + c4);
            split4(bv, &sm.Bh[r][c4], &sm.Bl[r][c4]);
        }
        __syncthreads();
        gemm_mainloop_k32(sm, acc, warp_m, warp_n, lane);
        __syncthreads();
    }
    gemm_epilogue<GELU>(acc, bias, C, N, m0, n0, warp_m, warp_n, lane);
}

// ============================================================================
// GRU — cluster version with xg prefetch-ahead + fast gates.
// 8 clusters x 16 CTAs x 256 thr; CTA owns 32 h-dims (96 W_hh rows in regs).
// h exchanged via DSMEM, double-buffered; split cluster arrive/wait.
// ============================================================================
__global__ void __launch_bounds__(256, 1)
gru_cluster_kernel(const float* __restrict__ xg, const float* __restrict__ W_hh,
                   const float* __restrict__ b_hh, float* __restrict__ memc) {
    __shared__ float hbuf[2][DQ];
    __shared__ float hg_sh[96];
    __shared__ float xg_sh[96];

    const int tid = threadIdx.x;
    const int w = tid >> 5, lane = tid & 31;
    const int rank = (int)my_ctarank();
    const int batch = blockIdx.x >> 4;
    const int d0 = rank * 32;

    // weights: warp w handles rows rr = w*12 .. w*12+11 (row = gate*32 + dim)
    unsigned long long wreg[12][8];
    #pragma unroll
    for (int rl = 0; rl < 12; rl++) {
        int rr = w * 12 + rl;
        int g = rr >> 5, di = rr & 31;
        const float* wp = W_hh + (size_t)(g * DQ + d0 + di) * DQ;
        #pragma unroll
        for (int j = 0; j < 8; j++) {
            float2 v = *reinterpret_cast<const float2*>(wp + j * 64 + lane * 2);
            wreg[rl][j] = pack2(v.x, v.y);
        }
    }

    float bh_r = 0.f, bh_z = 0.f, bh_n = 0.f;
    if (tid < 32) {
        bh_r = b_hh[d0 + tid];
        bh_z = b_hh[DQ + d0 + tid];
        bh_n = b_hh[2 * DQ + d0 + tid];
    }

    // xg indexing for this thread (tid<96): gate g, dim i
    const int xgi_g = tid >> 5, xgi_i = tid & 31;
    const size_t xg_stride = 3 * DQ;
    const size_t xg_base0 = (size_t)(batch * TQ) * xg_stride + xgi_g * DQ + d0 + xgi_i;

    // h_0 = 0
    hbuf[0][tid] = 0.f;
    hbuf[0][tid + 256] = 0.f;
    __syncthreads();
    CLUSTER_BARRIER_ARRIVE();
    CLUSTER_BARRIER_WAIT();

    // prefetch xg for t=0
    float xv_cur = 0.f;
    if (tid < 96) xv_cur = xg[xg_base0];

    for (int t = 0; t < TQ; t++) {
        // prefetch next step's xg (covered by this whole step)
        float xv_next = 0.f;
        if (tid < 96 && t + 1 < TQ) xv_next = xg[xg_base0 + (size_t)(t + 1) * xg_stride];

        if (t > 0) CLUSTER_BARRIER_WAIT();

        const float* hcur = hbuf[t & 1];
        unsigned long long acc[12];
        #pragma unroll
        for (int rl = 0; rl < 12; rl++) acc[rl] = 0ull;
        #pragma unroll
        for (int j = 0; j < 8; j++) {
            unsigned long long h2 =
                *reinterpret_cast<const unsigned long long*>(&hcur[j * 64 + lane * 2]);
            #pragma unroll
            for (int rl = 0; rl < 12; rl++) FMA2(acc[rl], h2, wreg[rl][j]);
        }
        #pragma unroll
        for (int rl = 0; rl < 12; rl++) {
            float x, y;
            unpack2(acc[rl], x, y);
            float s = x + y;
            #pragma unroll
            for (int off = 16; off > 0; off >>= 1)
                s += __shfl_xor_sync(0xffffffffu, s, off);
            if (lane == 0) hg_sh[w * 12 + rl] = s;
        }
        if (tid < 96) xg_sh[tid] = xv_cur;
        __syncthreads();

        float hnew = 0.f;
        if (tid < 32) {
            float hr = hg_sh[tid] + bh_r;
            float hz = hg_sh[32 + tid] + bh_z;
            float hn = hg_sh[64 + tid] + bh_n;
            float r = fast_sigmoid(xg_sh[tid] + hr);
            float z = fast_sigmoid(xg_sh[32 + tid] + hz);
            float n = fast_tanh(xg_sh[64 + tid] + r * hn);
            float hold = hcur[d0 + tid];
            hnew = (1.0f - z) * n + z * hold;
            uint32_t dst = smem_u32(&hbuf[(t + 1) & 1][d0 + tid]);
            #pragma unroll
            for (int p = 0; p < 16; p++) st_cluster_f32(dst, p, hnew);
        }
        CLUSTER_BARRIER_ARRIVE();

        // off the inter-CTA critical path
        if (tid < 32)
            memc[(size_t)(batch * TQ + t) * DQ + d0 + tid] = hnew;
        xv_cur = xv_next;
    }
    CLUSTER_BARRIER_WAIT();
}

// ---------------- legacy GRU (fallback; tree barrier) ----------------
__global__ void __launch_bounds__(256)
gru_kernel(const float* __restrict__ xg, const float* __restrict__ W_hh,
           const float* __restrict__ b_hh, float* __restrict__ memc) {
    __shared__ float h_sh[BQ * DQ];
    __shared__ float hg_sh[BQ * 12];

    const int tid = threadIdx.x;
    const int w = tid >> 5, lane = tid & 31;
    const int bp = w & 1, rh = w >> 1;
    const int d0 = blockIdx.x * 4;

    unsigned long long wreg[3][8];
    #pragma unroll
    for (int rl = 0; rl < 3; rl++) {
        int lr = rh * 3 + rl;
        int grow = (lr >> 2) * DQ + d0 + (lr & 3);
        const float* wp = W_hh + (size_t)grow * DQ;
        #pragma unroll
        for (int j = 0; j < 8; j++) {
            float2 v = *reinterpret_cast<const float2*>(wp + j * 64 + lane * 2);
            wreg[rl][j] = pack2(v.x, v.y);
        }
    }

    for (int t = 0; t < TQ; t++) {
        const float* hin = g_hbuf[t & 1];
        float* hout = g_hbuf[(t + 1) & 1];

        const float4* hp = reinterpret_cast<const float4*>(hin);
        #pragma unroll
        for (int v = 0; v < 4; v++)
            reinterpret_cast<float4*>(h_sh)[tid + v * 256] = hp[tid + v * 256];

        float xr = 0.f, xz = 0.f, xn = 0.f;
        if (tid < 32) {
            int b = tid >> 2, i = tid & 3;
            size_t base = ((size_t)(b * TQ + t)) * (3 * DQ) + d0 + i;
            xr = xg[base];
            xz = xg[base + DQ];
            xn = xg[base + 2 * DQ];
        }
        __syncthreads();

        unsigned long long acc[3][4];
        #pragma unroll
        for (int rl = 0; rl < 3; rl++)
            #pragma unroll
            for (int bb = 0; bb < 4; bb++) acc[rl][bb] = 0ull;

        #pragma unroll
        for (int j = 0; j < 8; j++) {
            unsigned long long h2[4];
            #pragma unroll
            for (int bb = 0; bb < 4; bb++)
                h2[bb] = *reinterpret_cast<const unsigned long long*>(
                    &h_sh[(bp * 4 + bb) * DQ + j * 64 + lane * 2]);
            #pragma unroll
            for (int rl = 0; rl < 3; rl++)
                #pragma unroll
                for (int bb = 0; bb < 4; bb++)
                    FMA2(acc[rl][bb], h2[bb], wreg[rl][j]);
        }

        #pragma unroll
        for (int rl = 0; rl < 3; rl++)
            #pragma unroll
            for (int bb = 0; bb < 4; bb++) {
                float x, y;
                unpack2(acc[rl][bb], x, y);
                float s = x + y;
                #pragma unroll
                for (int off = 16; off > 0; off >>= 1)
                    s += __shfl_xor_sync(0xffffffffu, s, off);
                if (lane == 0) hg_sh[(bp * 4 + bb) * 12 + rh * 3 + rl] = s;
            }
        __syncthreads();

        if (tid < 32) {
            int b = tid >> 2, i = tid & 3;
            int d = d0 + i;
            float hr = hg_sh[b * 12 + i]     + b_hh[d];
            float hz = hg_sh[b * 12 + 4 + i] + b_hh[DQ + d];
            float hn = hg_sh[b * 12 + 8 + i] + b_hh[2 * DQ + d];
            float r = 1.0f / (1.0f + expf(-(xr + hr)));
            float z = 1.0f / (1.0f + expf(-(xz + hz)));
            float n = tanhf(xn + r * hn);
            float hold = h_sh[b * DQ + d];
            float hnew = (1.0f - z) * n + z * hold;
            hout[b * DQ + d] = hnew;
            memc[((size_t)(b * TQ + t)) * DQ + d] = hnew;
        }
        __syncthreads();

        if (tid == 0) {
            __threadfence();
            const unsigned step = (unsigned)(t + 1);
            const int g = blockIdx.x >> 3;
            unsigned a = atomicAdd(&g_grp[g], 1u) + 1u;
            if (a == step * 8u) {
                unsigned r = atomicAdd(&g_root, 1u) + 1u;
                if (r == step * 16u) {
                    g_sense = step;
                }
            }
            int spins = 0;
            while (g_sense < step) {
                if (++spins > 32) __nanosleep(32);
            }
            __threadfence();
        }
        __syncthreads();
    }
}

__global__ void reset_kernel() {
    int tid = threadIdx.x;
    for (int i = tid; i < BQ * DQ; i += blockDim.x) {
        g_hbuf[0][i] = 0.0f;
        g_hbuf[1][i] = 0.0f;
    }
    if (tid < 16) g_grp[tid] = 0u;
    if (tid == 0) { g_root = 0u; g_sense = 0u; }
}

// ---------------- final residual + LN ----------------
__global__ void final_kernel(const float* __restrict__ emb, const float* __restrict__ fused,
                             const float* __restrict__ change,
                             const float* __restrict__ ln_g, const float* __restrict__ ln_b,
                             float* __restrict__ out) {
    __shared__ float red[16];
    const int token = blockIdx.x;
    const int d = threadIdx.x;
    const size_t base = (size_t)token * DQ + d;
    float x = emb[base] + fused[base] + change[base];
    float mu = block_sum_512(x, red) * (1.0f / DQ);
    float dv = x - mu;
    float var = block_sum_512(dv * dv, red) * (1.0f / DQ);
    out[base] = dv * rsqrtf(var + 1e-5f) * ln_g[d] + ln_b[d];
}

// ---------------- launch ----------------
static float* symp(const void* sym) {
    void* p = nullptr;
    cudaGetSymbolAddress(&p, sym);
    return (float*)p;
}

extern "C" void kernel_launch(void* const* d_in, const int* in_sizes, int n_in,
                              void* d_out, int out_size) {
    const float* emb   = (const float*)d_in[0];
    const float* w_s   = (const float*)d_in[1];
    const float* b_s   = (const float*)d_in[2];
    const float* gs    = (const float*)d_in[3];
    const float* bes   = (const float*)d_in[4];
    const float* w_m   = (const float*)d_in[5];
    const float* b_m   = (const float*)d_in[6];
    const float* gm    = (const float*)d_in[7];
    const float* bem   = (const float*)d_in[8];
    const float* w_l   = (const float*)d_in[9];
    const float* b_l   = (const float*)d_in[10];
    const float* gl    = (const float*)d_in[11];
    const float* bel   = (const float*)d_in[12];
    const float* W_ih  = (const float*)d_in[13];
    const float* W_hh  = (const float*)d_in[14];
    const float* b_ih  = (const float*)d_in[15];
    const float* b_hh  = (const float*)d_in[16];
    const float* ce_w1 = (const float*)d_in[17];
    const float* ce_b1 = (const float*)d_in[18];
    const float* ce_w2 = (const float*)d_in[19];
    const float* ce_b2 = (const float*)d_in[20];
    const float* fu_w1 = (const float*)d_in[21];
    const float* fu_b1 = (const float*)d_in[22];
    const float* fu_w2 = (const float*)d_in[23];
    const float* fu_b2 = (const float*)d_in[24];
    const float* ln_g  = (const float*)d_in[25];
    const float* ln_b  = (const float*)d_in[26];

    float* sctx   = symp(g_short);
    float* mctx   = symp(g_mid);
    float* lctx   = symp(g_long);
    float* memc   = symp(g_memc);
    float* change = symp(g_change);
    float* fused  = symp(g_fused);
    float* xg     = symp(g_xg);
    float* h1     = symp(g_h1);
    float* fh     = symp(g_fh);

    // multi-scale conv + LN
    ctx_kernel<<<NTOK, 512>>>(emb, w_s, b_s, gs, bes, w_m, b_m, gm, bem,
                              w_l, b_l, gl, bel, sctx, mctx, lctx);

    // xg = emb @ W_ih^T + b_ih
    gemm_bf16_kernel<false><<<dim3(12, 128), 256>>>(emb, W_ih, b_ih, xg, NTOK, 1536, 512);

    // change path
    {
        SegPtrs sp{};
        sp.p[0] = emb; sp.p[1] = emb;
        seg_gemm_bf16_kernel<true, true><<<dim3(2, 128), 256>>>(sp, ce_w1, ce_b1, h1,
                                                                NTOK, 256, 1024);
    }
    gemm_bf16_kernel<false><<<dim3(4, 128), 256>>>(h1, ce_w2, ce_b2, change, NTOK, 512, 256);

    // GRU recurrence: cluster path if 16-CTA clusters supported, else legacy.
    reset_kernel<<<1, 256>>>();
    {
        cudaFuncSetAttribute(gru_cluster_kernel,
                             cudaFuncAttributeNonPortableClusterSizeAllowed, 1);
        cudaLaunchConfig_t cfg = {};
        cfg.gridDim = dim3(GRU_CTAS, 1, 1);
        cfg.blockDim = dim3(256, 1, 1);
        cfg.dynamicSmemBytes = 0;
        cfg.stream = 0;
        cudaLaunchAttribute attrs[1];
        attrs[0].id = cudaLaunchAttributeClusterDimension;
        attrs[0].val.clusterDim.x = 16;
        attrs[0].val.clusterDim.y = 1;
        attrs[0].val.clusterDim.z = 1;
        cfg.attrs = attrs;
        cfg.numAttrs = 1;

        int nclust = 0;
        cudaError_t qe = cudaOccupancyMaxActiveClusters(&nclust, gru_cluster_kernel, &cfg);
        if (qe != cudaSuccess) { (void)cudaGetLastError(); nclust = 0; }

        if (nclust >= 1) {
            cudaLaunchKernelEx(&cfg, gru_cluster_kernel, xg, W_hh, b_hh, memc);
        } else {
            gru_kernel<<<GRU_CTAS, 256>>>(xg, W_hh, b_hh, memc);
        }
    }

    // fusion path
    {
        SegPtrs sp{};
        sp.p[0] = emb; sp.p[1] = sctx; sp.p[2] = mctx; sp.p[3] = lctx; sp.p[4] = memc;
        seg_gemm_bf16_kernel<true, false><<<dim3(8, 128), 256>>>(sp, fu_w1, fu_b1, fh,
                                                                 NTOK, 1024, 2560);
    }
    gemm_bf16_kernel<false><<<dim3(4, 128), 256>>>(fh, fu_w2, fu_b2, fused, NTOK, 512, 1024);

    // out = LN(emb + fused + change)
    final_kernel<<<NTOK, 512>>>(emb, fused, change, ln_g, ln_b, (float*)d_out);
}

// round 10
// speedup vs baseline: 2.6502x; 1.1256x over previous
#include <cuda_runtime.h>
#include <cuda_bf16.h>
#include <math.h>
#include <stdint.h>

#define BQ 8
#define TQ 2048
#define DQ 512
#define NTOK (BQ * TQ)            // 16384
#define GRU_CTAS 128

// ---------------- scratch (device globals; allocation-free) ----------------
__device__ float g_short[NTOK * DQ];
__device__ float g_mid[NTOK * DQ];
__device__ float g_long[NTOK * DQ];
__device__ float g_memc[NTOK * DQ];
__device__ float g_change[NTOK * DQ];
__device__ float g_fused[NTOK * DQ];
__device__ float g_xg[NTOK * 3 * DQ];
__device__ float g_h1[NTOK * 256];
__device__ float g_fh[NTOK * 1024];
__device__ float g_hbuf[2][BQ * DQ];
__device__ unsigned g_grp[16];              // legacy tree barrier
__device__ unsigned g_root;
__device__ volatile unsigned g_sense;

struct SegPtrs { const float* p[5]; };

// ---------------- helpers ----------------
__device__ __forceinline__ float gelu_exact(float x) {
    return 0.5f * x * (1.0f + erff(x * 0.70710678118654752440f));
}

#define FMA2(d, a, b) asm("fma.rn.f32x2 %0, %1, %2, %0;" : "+l"(d) : "l"(a), "l"(b))

__device__ __forceinline__ unsigned long long pack2(float x, float y) {
    unsigned long long r;
    asm("mov.b64 %0, {%1, %2};" : "=l"(r) : "r"(__float_as_uint(x)), "r"(__float_as_uint(y)));
    return r;
}
__device__ __forceinline__ void unpack2(unsigned long long v, float& x, float& y) {
    unsigned lo, hi;
    asm("mov.b64 {%0, %1}, %2;" : "=r"(lo), "=r"(hi) : "l"(v));
    x = __uint_as_float(lo); y = __uint_as_float(hi);
}

__device__ __forceinline__ float block_sum_512(float v, float* red) {
    int lane = threadIdx.x & 31, w = threadIdx.x >> 5;
    #pragma unroll
    for (int off = 16; off > 0; off >>= 1) v += __shfl_xor_sync(0xffffffffu, v, off);
    if (lane == 0) red[w] = v;
    __syncthreads();
    float s = (threadIdx.x < 16) ? red[threadIdx.x] : 0.0f;
    if (w == 0) {
        #pragma unroll
        for (int off = 8; off > 0; off >>= 1) s += __shfl_xor_sync(0xffffffffu, s, off);
        if (lane == 0) red[0] = s;
    }
    __syncthreads();
    float r = red[0];
    __syncthreads();
    return r;
}

__device__ __forceinline__ uint32_t smem_u32(const void* p) {
    return (uint32_t)__cvta_generic_to_shared(p);
}

__device__ __forceinline__ uint32_t my_ctarank() {
    uint32_t r; asm("mov.u32 %0, %%cluster_ctarank;" : "=r"(r)); return r;
}

__device__ __forceinline__ void st_cluster_f32(uint32_t local_smem_addr, int peer, float v) {
    uint32_t remote;
    asm volatile("mapa.shared::cluster.u32 %0, %1, %2;"
                 : "=r"(remote) : "r"(local_smem_addr), "r"(peer));
    asm volatile("st.shared::cluster.f32 [%0], %1;" :: "r"(remote), "f"(v) : "memory");
}

#define MBARRIER_INIT(mbar_smem_addr, count) \
    asm volatile("mbarrier.init.shared.b64 [%0], %1;" \
                 :: "r"((uint32_t)(mbar_smem_addr)), "r"((uint32_t)(count)) : "memory")

// remote arrive on peer's mbarrier at same smem offset (release, cluster scope)
__device__ __forceinline__ void mbar_arrive_peer(uint32_t local_mbar_addr, int peer) {
    uint32_t rem;
    asm volatile("mapa.shared::cluster.u32 %0, %1, %2;"
                 : "=r"(rem) : "r"(local_mbar_addr), "r"(peer));
    asm volatile("mbarrier.arrive.shared::cluster.b64 _, [%0];"
                 :: "r"(rem) : "memory");
}

// local parity wait (acquire) — HW-sleep try_wait loop
__device__ __forceinline__ void mbar_wait_parity(uint32_t mbar_addr, uint32_t parity) {
    asm volatile(
        "{\n\t"
        ".reg .pred P1;\n\t"
        "WAIT_LOOP_%=:\n\t"
        "mbarrier.try_wait.parity.acquire.cta.shared::cta.b64 P1, [%0], %1, 0x989680;\n\t"
        "@P1 bra.uni WAIT_DONE_%=;\n\t"
        "bra.uni WAIT_LOOP_%=;\n\t"
        "WAIT_DONE_%=:\n\t"
        "}"
        :: "r"(mbar_addr), "r"(parity) : "memory");
}

#define CLUSTER_BARRIER_ARRIVE() \
    asm volatile("barrier.cluster.arrive.aligned;" ::: "memory")
#define CLUSTER_BARRIER_WAIT() \
    asm volatile("barrier.cluster.wait.aligned;" ::: "memory")

#define LDSM4(r0, r1, r2, r3, addr) \
    asm volatile("ldmatrix.sync.aligned.m8n8.x4.shared.b16 {%0,%1,%2,%3},[%4];" \
                 : "=r"(r0), "=r"(r1), "=r"(r2), "=r"(r3) : "r"(addr))

#define MMA16816(d, a, b) \
    asm volatile("mma.sync.aligned.m16n8k16.row.col.f32.bf16.bf16.f32 " \
                 "{%0,%1,%2,%3},{%4,%5,%6,%7},{%8,%9},{%0,%1,%2,%3};" \
                 : "+f"((d)[0]), "+f"((d)[1]), "+f"((d)[2]), "+f"((d)[3]) \
                 : "r"((a)[0]), "r"((a)[1]), "r"((a)[2]), "r"((a)[3]), \
                   "r"((b)[0]), "r"((b)[1]))

__device__ __forceinline__ void split4(float4 v, __nv_bfloat16* hi, __nv_bfloat16* lo) {
    float x[4] = {v.x, v.y, v.z, v.w};
    #pragma unroll
    for (int i = 0; i < 4; i++) {
        __nv_bfloat16 h = __float2bfloat16(x[i]);
        hi[i] = h;
        lo[i] = __float2bfloat16(x[i] - __bfloat162float(h));
    }
}

__device__ __forceinline__ float fast_sigmoid(float x) {
    return __fdividef(1.0f, 1.0f + __expf(-x));
}
__device__ __forceinline__ float fast_tanh(float x) {
    return 2.0f * __fdividef(1.0f, 1.0f + __expf(-2.0f * x)) - 1.0f;
}

// ---------------- conv (3 scales) + per-scale LN, fused ----------------
__global__ void ctx_kernel(const float* __restrict__ emb,
                           const float* __restrict__ w_s, const float* __restrict__ b_s,
                           const float* __restrict__ g_s, const float* __restrict__ be_s,
                           const float* __restrict__ w_m, const float* __restrict__ b_m,
                           const float* __restrict__ g_m, const float* __restrict__ be_m,
                           const float* __restrict__ w_l, const float* __restrict__ b_l,
                           const float* __restrict__ g_l, const float* __restrict__ be_l,
                           float* __restrict__ out_s, float* __restrict__ out_m,
                           float* __restrict__ out_l) {
    __shared__ float red[16];
    const int token = blockIdx.x;
    const int t = token & (TQ - 1);
    const int d = threadIdx.x;

    float xr[32];
    #pragma unroll
    for (int j = 0; j < 32; j++)
        xr[j] = (t - j >= 0) ? emb[((size_t)(token - j)) * DQ + d] : 0.0f;

    float ys = b_s[d], ym = b_m[d], yl = b_l[d];
    #pragma unroll
    for (int j = 0; j < 2; j++)  ys += w_s[d * 2 + 1 - j] * xr[j];
    #pragma unroll
    for (int j = 0; j < 8; j++)  ym += w_m[d * 8 + 7 - j] * xr[j];
    #pragma unroll
    for (int j = 0; j < 32; j++) yl += w_l[d * 32 + 31 - j] * xr[j];

    const size_t base = (size_t)token * DQ + d;
    {
        float mu = block_sum_512(ys, red) * (1.0f / DQ);
        float dv = ys - mu;
        float var = block_sum_512(dv * dv, red) * (1.0f / DQ);
        out_s[base] = dv * rsqrtf(var + 1e-5f) * g_s[d] + be_s[d];
    }
    {
        float mu = block_sum_512(ym, red) * (1.0f / DQ);
        float dv = ym - mu;
        float var = block_sum_512(dv * dv, red) * (1.0f / DQ);
        out_m[base] = dv * rsqrtf(var + 1e-5f) * g_m[d] + be_m[d];
    }
    {
        float mu = block_sum_512(yl, red) * (1.0f / DQ);
        float dv = yl - mu;
        float var = block_sum_512(dv * dv, red) * (1.0f / DQ);
        out_l[base] = dv * rsqrtf(var + 1e-5f) * g_l[d] + be_l[d];
    }
}

// ============================================================================
// Tensor-core GEMM (unchanged — known good)
// ============================================================================
struct GemmSmem {
    __nv_bfloat16 Ah[128][40];
    __nv_bfloat16 Al[128][40];
    __nv_bfloat16 Bh[128][40];
    __nv_bfloat16 Bl[128][40];
};

__device__ __forceinline__ void gemm_mainloop_k32(
    GemmSmem& sm, float acc[2][8][4], int warp_m, int warp_n, int lane) {
    #pragma unroll
    for (int ks = 0; ks < 32; ks += 16) {
        const int arow = (lane & 15);
        const int acol = ks + (lane >> 4) * 8;
        uint32_t ah[2][4], al[2][4];
        #pragma unroll
        for (int mi = 0; mi < 2; mi++) {
            int mb = warp_m * 32 + mi * 16;
            uint32_t addr_h = smem_u32(&sm.Ah[mb + arow][acol]);
            uint32_t addr_l = smem_u32(&sm.Al[mb + arow][acol]);
            LDSM4(ah[mi][0], ah[mi][1], ah[mi][2], ah[mi][3], addr_h);
            LDSM4(al[mi][0], al[mi][1], al[mi][2], al[mi][3], addr_l);
        }
        #pragma unroll
        for (int pair = 0; pair < 4; pair++) {
            int nb = warp_n * 64 + pair * 16;
            uint32_t bh[4], bl[4];
            uint32_t baddr_h = smem_u32(&sm.Bh[nb + arow][acol]);
            uint32_t baddr_l = smem_u32(&sm.Bl[nb + arow][acol]);
            LDSM4(bh[0], bh[1], bh[2], bh[3], baddr_h);
            LDSM4(bl[0], bl[1], bl[2], bl[3], baddr_l);
            uint32_t bEh[2] = {bh[0], bh[2]}, bOh[2] = {bh[1], bh[3]};
            uint32_t bEl[2] = {bl[0], bl[2]}, bOl[2] = {bl[1], bl[3]};
            #pragma unroll
            for (int mi = 0; mi < 2; mi++) {
                MMA16816(acc[mi][2 * pair],     ah[mi], bEh);
                MMA16816(acc[mi][2 * pair],     ah[mi], bEl);
                MMA16816(acc[mi][2 * pair],     al[mi], bEh);
                MMA16816(acc[mi][2 * pair + 1], ah[mi], bOh);
                MMA16816(acc[mi][2 * pair + 1], ah[mi], bOl);
                MMA16816(acc[mi][2 * pair + 1], al[mi], bOh);
            }
        }
    }
}

template <bool GELU>
__device__ __forceinline__ void gemm_epilogue(
    float acc[2][8][4], const float* __restrict__ bias, float* __restrict__ C,
    int N, int m0, int n0, int warp_m, int warp_n, int lane) {
    const int g = lane >> 2, tg = lane & 3;
    #pragma unroll
    for (int mi = 0; mi < 2; mi++) {
        #pragma unroll
        for (int ni = 0; ni < 8; ni++) {
            int row = m0 + warp_m * 32 + mi * 16 + g;
            int col = n0 + warp_n * 64 + ni * 8 + tg * 2;
            float b0 = bias[col], b1 = bias[col + 1];
            float v0 = acc[mi][ni][0] + b0, v1 = acc[mi][ni][1] + b1;
            float v2 = acc[mi][ni][2] + b0, v3 = acc[mi][ni][3] + b1;
            if (GELU) {
                v0 = gelu_exact(v0); v1 = gelu_exact(v1);
                v2 = gelu_exact(v2); v3 = gelu_exact(v3);
            }
            *reinterpret_cast<float2*>(&C[(size_t)row * N + col]) = make_float2(v0, v1);
            *reinterpret_cast<float2*>(&C[(size_t)(row + 8) * N + col]) = make_float2(v2, v3);
        }
    }
}

template <bool GELU>
__global__ __launch_bounds__(256)
void gemm_bf16_kernel(const float* __restrict__ A, const float* __restrict__ W,
                      const float* __restrict__ bias, float* __restrict__ C,
                      int M, int N, int K) {
    __shared__ GemmSmem sm;
    const int tid = threadIdx.x;
    const int lane = tid & 31, wid = tid >> 5;
    const int warp_m = wid >> 1, warp_n = wid & 1;
    const int m0 = blockIdx.y * 128, n0 = blockIdx.x * 128;

    float acc[2][8][4];
    #pragma unroll
    for (int mi = 0; mi < 2; mi++)
        #pragma unroll
        for (int ni = 0; ni < 8; ni++)
            #pragma unroll
            for (int j = 0; j < 4; j++) acc[mi][ni][j] = 0.0f;

    for (int k0 = 0; k0 < K; k0 += 32) {
        #pragma unroll
        for (int v = 0; v < 4; v++) {
            int f = v * 256 + tid;
            int r = f >> 3, c4 = (f & 7) << 2;
            float4 av = *reinterpret_cast<const float4*>(A + (size_t)(m0 + r) * K + k0 + c4);
            split4(av, &sm.Ah[r][c4], &sm.Al[r][c4]);
            float4 bv = *reinterpret_cast<const float4*>(W + (size_t)(n0 + r) * K + k0 + c4);
            split4(bv, &sm.Bh[r][c4], &sm.Bl[r][c4]);
        }
        __syncthreads();
        gemm_mainloop_k32(sm, acc, warp_m, warp_n, lane);
        __syncthreads();
    }
    gemm_epilogue<GELU>(acc, bias, C, N, m0, n0, warp_m, warp_n, lane);
}

template <bool GELU, bool PREV>
__global__ __launch_bounds__(256)
void seg_gemm_bf16_kernel(SegPtrs segs, const float* __restrict__ W,
                          const float* __restrict__ bias, float* __restrict__ C,
                          int M, int N, int K) {
    __shared__ GemmSmem sm;
    const int tid = threadIdx.x;
    const int lane = tid & 31, wid = tid >> 5;
    const int warp_m = wid >> 1, warp_n = wid & 1;
    const int m0 = blockIdx.y * 128, n0 = blockIdx.x * 128;

    float acc[2][8][4];
    #pragma unroll
    for (int mi = 0; mi < 2; mi++)
        #pragma unroll
        for (int ni = 0; ni < 8; ni++)
            #pragma unroll
            for (int j = 0; j < 4; j++) acc[mi][ni][j] = 0.0f;

    for (int k0 = 0; k0 < K; k0 += 32) {
        const int seg = k0 >> 9;
        const int ks = k0 & 511;
        const float* __restrict__ Aseg = segs.p[seg];
        #pragma unroll
        for (int v = 0; v < 4; v++) {
            int f = v * 256 + tid;
            int r = f >> 3, c4 = (f & 7) << 2;
            int m = m0 + r;
            if (PREV && seg == 1) m = ((m & (TQ - 1)) == 0) ? m : m - 1;
            float4 av = *reinterpret_cast<const float4*>(Aseg + (size_t)m * DQ + ks + c4);
            split4(av, &sm.Ah[r][c4], &sm.Al[r][c4]);
            float4 bv = *reinterpret_cast<const float4*>(W + (size_t)(n0 + r) * K + k0 + c4);
            split4(bv, &sm.Bh[r][c4], &sm.Bl[r][c4]);
        }
        __syncthreads();
        gemm_mainloop_k32(sm, acc, warp_m, warp_n, lane);
        __syncthreads();
    }
    gemm_epilogue<GELU>(acc, bias, C, N, m0, n0, warp_m, warp_n, lane);
}

// ============================================================================
// GRU — cluster version with per-CTA mbarrier signaling (2-deep pipeline).
// 8 clusters x 16 CTAs x 256 thr; CTA owns 32 h-dims (96 W_hh rows in regs).
// Per step: warp0 DSMEM-stores h to all peers; lanes 0-15 remote-arrive on
// peers' mbar; consumers try_wait locally. No per-step cluster rendezvous.
// ============================================================================
__global__ void __launch_bounds__(256, 1)
gru_cluster_kernel(const float* __restrict__ xg, const float* __restrict__ W_hh,
                   const float* __restrict__ b_hh, float* __restrict__ memc) {
    __shared__ float hbuf[2][DQ];
    __shared__ float hg_sh[96];
    __shared__ float xg_sh[96];
    __shared__ __align__(8) unsigned long long mbar[2];

    const int tid = threadIdx.x;
    const int w = tid >> 5, lane = tid & 31;
    const int rank = (int)my_ctarank();
    const int batch = blockIdx.x >> 4;
    const int d0 = rank * 32;

    // weights: warp w handles rows rr = w*12 .. w*12+11 (row = gate*32 + dim)
    unsigned long long wreg[12][8];
    #pragma unroll
    for (int rl = 0; rl < 12; rl++) {
        int rr = w * 12 + rl;
        int g = rr >> 5, di = rr & 31;
        const float* wp = W_hh + (size_t)(g * DQ + d0 + di) * DQ;
        #pragma unroll
        for (int j = 0; j < 8; j++) {
            float2 v = *reinterpret_cast<const float2*>(wp + j * 64 + lane * 2);
            wreg[rl][j] = pack2(v.x, v.y);
        }
    }

    float bh_r = 0.f, bh_z = 0.f, bh_n = 0.f;
    if (tid < 64) {
        int l = tid & 31;
        bh_r = b_hh[d0 + l];
        bh_z = b_hh[DQ + d0 + l];
        bh_n = b_hh[2 * DQ + d0 + l];
    }

    const int xgi_g = tid >> 5, xgi_i = tid & 31;
    const size_t xg_stride = 3 * DQ;
    const size_t xg_base0 = (size_t)(batch * TQ) * xg_stride + xgi_g * DQ + d0 + xgi_i;

    // init mbarriers + h_0 = 0
    if (tid == 0) {
        MBARRIER_INIT(smem_u32(&mbar[0]), 16);
        MBARRIER_INIT(smem_u32(&mbar[1]), 16);
    }
    hbuf[0][tid] = 0.f;
    hbuf[0][tid + 256] = 0.f;
    __syncthreads();
    CLUSTER_BARRIER_ARRIVE();
    CLUSTER_BARRIER_WAIT();

    float xv_cur = 0.f;
    if (tid < 96) xv_cur = xg[xg_base0];
    int ph0 = 0, ph1 = 0;

    for (int t = 0; t < TQ; t++) {
        // prefetch next step's xg (covered by this whole step)
        float xv_next = 0.f;
        if (tid < 96 && t + 1 < TQ) xv_next = xg[xg_base0 + (size_t)(t + 1) * xg_stride];

        // wait for h_t (delivered into hbuf[t&1] by all peers during step t-1)
        if (t > 0) {
            if (t & 1) { mbar_wait_parity(smem_u32(&mbar[1]), (uint32_t)ph1); ph1 ^= 1; }
            else       { mbar_wait_parity(smem_u32(&mbar[0]), (uint32_t)ph0); ph0 ^= 1; }
        }

        const float* hcur = hbuf[t & 1];
        unsigned long long acc[12];
        #pragma unroll
        for (int rl = 0; rl < 12; rl++) acc[rl] = 0ull;
        #pragma unroll
        for (int j = 0; j < 8; j++) {
            unsigned long long h2 =
                *reinterpret_cast<const unsigned long long*>(&hcur[j * 64 + lane * 2]);
            #pragma unroll
            for (int rl = 0; rl < 12; rl++) FMA2(acc[rl], h2, wreg[rl][j]);
        }
        #pragma unroll
        for (int rl = 0; rl < 12; rl++) {
            float x, y;
            unpack2(acc[rl], x, y);
            float s = x + y;
            #pragma unroll
            for (int off = 16; off > 0; off >>= 1)
                s += __shfl_xor_sync(0xffffffffu, s, off);
            if (lane == 0) hg_sh[w * 12 + rl] = s;
        }
        if (tid < 96) xg_sh[tid] = xv_cur;
        __syncthreads();   // A: hg/xg ready

        // warps 0 and 1 both compute hnew (warp0 -> DSMEM, warp1 -> memc)
        float hnew = 0.f;
        if (tid < 64) {
            int l = tid & 31;
            float hr = hg_sh[l] + bh_r;
            float hz = hg_sh[32 + l] + bh_z;
            float hn = hg_sh[64 + l] + bh_n;
            float r = fast_sigmoid(xg_sh[l] + hr);
            float z = fast_sigmoid(xg_sh[32 + l] + hz);
            float n = fast_tanh(xg_sh[64 + l] + r * hn);
            float hold = hcur[d0 + l];
            hnew = (1.0f - z) * n + z * hold;
        }
        if (tid >= 32 && tid < 64)
            memc[(size_t)(batch * TQ + t) * DQ + d0 + (tid & 31)] = hnew;
        if (tid < 32 && t + 1 < TQ) {
            uint32_t dst = smem_u32(&hbuf[(t + 1) & 1][d0 + tid]);
            #pragma unroll
            for (int p = 0; p < 16; p++) st_cluster_f32(dst, p, hnew);
        }
        __syncthreads();   // B: stores done (cumulativity for the arrives)

        if (tid < 16 && t + 1 < TQ)
            mbar_arrive_peer(smem_u32(&mbar[(t + 1) & 1]), tid);

        xv_cur = xv_next;
    }
    CLUSTER_BARRIER_ARRIVE();
    CLUSTER_BARRIER_WAIT();
}

// ---------------- legacy GRU (fallback; tree barrier) ----------------
__global__ void __launch_bounds__(256)
gru_kernel(const float* __restrict__ xg, const float* __restrict__ W_hh,
           const float* __restrict__ b_hh, float* __restrict__ memc) {
    __shared__ float h_sh[BQ * DQ];
    __shared__ float hg_sh[BQ * 12];

    const int tid = threadIdx.x;
    const int w = tid >> 5, lane = tid & 31;
    const int bp = w & 1, rh = w >> 1;
    const int d0 = blockIdx.x * 4;

    unsigned long long wreg[3][8];
    #pragma unroll
    for (int rl = 0; rl < 3; rl++) {
        int lr = rh * 3 + rl;
        int grow = (lr >> 2) * DQ + d0 + (lr & 3);
        const float* wp = W_hh + (size_t)grow * DQ;
        #pragma unroll
        for (int j = 0; j < 8; j++) {
            float2 v = *reinterpret_cast<const float2*>(wp + j * 64 + lane * 2);
            wreg[rl][j] = pack2(v.x, v.y);
        }
    }

    for (int t = 0; t < TQ; t++) {
        const float* hin = g_hbuf[t & 1];
        float* hout = g_hbuf[(t + 1) & 1];

        const float4* hp = reinterpret_cast<const float4*>(hin);
        #pragma unroll
        for (int v = 0; v < 4; v++)
            reinterpret_cast<float4*>(h_sh)[tid + v * 256] = hp[tid + v * 256];

        float xr = 0.f, xz = 0.f, xn = 0.f;
        if (tid < 32) {
            int b = tid >> 2, i = tid & 3;
            size_t base = ((size_t)(b * TQ + t)) * (3 * DQ) + d0 + i;
            xr = xg[base];
            xz = xg[base + DQ];
            xn = xg[base + 2 * DQ];
        }
        __syncthreads();

        unsigned long long acc[3][4];
        #pragma unroll
        for (int rl = 0; rl < 3; rl++)
            #pragma unroll
            for (int bb = 0; bb < 4; bb++) acc[rl][bb] = 0ull;

        #pragma unroll
        for (int j = 0; j < 8; j++) {
            unsigned long long h2[4];
            #pragma unroll
            for (int bb = 0; bb < 4; bb++)
                h2[bb] = *reinterpret_cast<const unsigned long long*>(
                    &h_sh[(bp * 4 + bb) * DQ + j * 64 + lane * 2]);
            #pragma unroll
            for (int rl = 0; rl < 3; rl++)
                #pragma unroll
                for (int bb = 0; bb < 4; bb++)
                    FMA2(acc[rl][bb], h2[bb], wreg[rl][j]);
        }

        #pragma unroll
        for (int rl = 0; rl < 3; rl++)
            #pragma unroll
            for (int bb = 0; bb < 4; bb++) {
                float x, y;
                unpack2(acc[rl][bb], x, y);
                float s = x + y;
                #pragma unroll
                for (int off = 16; off > 0; off >>= 1)
                    s += __shfl_xor_sync(0xffffffffu, s, off);
                if (lane == 0) hg_sh[(bp * 4 + bb) * 12 + rh * 3 + rl] = s;
            }
        __syncthreads();

        if (tid < 32) {
            int b = tid >> 2, i = tid & 3;
            int d = d0 + i;
            float hr = hg_sh[b * 12 + i]     + b_hh[d];
            float hz = hg_sh[b * 12 + 4 + i] + b_hh[DQ + d];
            float hn = hg_sh[b * 12 + 8 + i] + b_hh[2 * DQ + d];
            float r = 1.0f / (1.0f + expf(-(xr + hr)));
            float z = 1.0f / (1.0f + expf(-(xz + hz)));
            float n = tanhf(xn + r * hn);
            float hold = h_sh[b * DQ + d];
            float hnew = (1.0f - z) * n + z * hold;
            hout[b * DQ + d] = hnew;
            memc[((size_t)(b * TQ + t)) * DQ + d] = hnew;
        }
        __syncthreads();

        if (tid == 0) {
            __threadfence();
            const unsigned step = (unsigned)(t + 1);
            const int g = blockIdx.x >> 3;
            unsigned a = atomicAdd(&g_grp[g], 1u) + 1u;
            if (a == step * 8u) {
                unsigned r = atomicAdd(&g_root, 1u) + 1u;
                if (r == step * 16u) {
                    g_sense = step;
                }
            }
            int spins = 0;
            while (g_sense < step) {
                if (++spins > 32) __nanosleep(32);
            }
            __threadfence();
        }
        __syncthreads();
    }
}

__global__ void reset_kernel() {
    int tid = threadIdx.x;
    for (int i = tid; i < BQ * DQ; i += blockDim.x) {
        g_hbuf[0][i] = 0.0f;
        g_hbuf[1][i] = 0.0f;
    }
    if (tid < 16) g_grp[tid] = 0u;
    if (tid == 0) { g_root = 0u; g_sense = 0u; }
}

// ---------------- final residual + LN ----------------
__global__ void final_kernel(const float* __restrict__ emb, const float* __restrict__ fused,
                             const float* __restrict__ change,
                             const float* __restrict__ ln_g, const float* __restrict__ ln_b,
                             float* __restrict__ out) {
    __shared__ float red[16];
    const int token = blockIdx.x;
    const int d = threadIdx.x;
    const size_t base = (size_t)token * DQ + d;
    float x = emb[base] + fused[base] + change[base];
    float mu = block_sum_512(x, red) * (1.0f / DQ);
    float dv = x - mu;
    float var = block_sum_512(dv * dv, red) * (1.0f / DQ);
    out[base] = dv * rsqrtf(var + 1e-5f) * ln_g[d] + ln_b[d];
}

// ---------------- launch ----------------
static float* symp(const void* sym) {
    void* p = nullptr;
    cudaGetSymbolAddress(&p, sym);
    return (float*)p;
}

extern "C" void kernel_launch(void* const* d_in, const int* in_sizes, int n_in,
                              void* d_out, int out_size) {
    const float* emb   = (const float*)d_in[0];
    const float* w_s   = (const float*)d_in[1];
    const float* b_s   = (const float*)d_in[2];
    const float* gs    = (const float*)d_in[3];
    const float* bes   = (const float*)d_in[4];
    const float* w_m   = (const float*)d_in[5];
    const float* b_m   = (const float*)d_in[6];
    const float* gm    = (const float*)d_in[7];
    const float* bem   = (const float*)d_in[8];
    const float* w_l   = (const float*)d_in[9];
    const float* b_l   = (const float*)d_in[10];
    const float* gl    = (const float*)d_in[11];
    const float* bel   = (const float*)d_in[12];
    const float* W_ih  = (const float*)d_in[13];
    const float* W_hh  = (const float*)d_in[14];
    const float* b_ih  = (const float*)d_in[15];
    const float* b_hh  = (const float*)d_in[16];
    const float* ce_w1 = (const float*)d_in[17];
    const float* ce_b1 = (const float*)d_in[18];
    const float* ce_w2 = (const float*)d_in[19];
    const float* ce_b2 = (const float*)d_in[20];
    const float* fu_w1 = (const float*)d_in[21];
    const float* fu_b1 = (const float*)d_in[22];
    const float* fu_w2 = (const float*)d_in[23];
    const float* fu_b2 = (const float*)d_in[24];
    const float* ln_g  = (const float*)d_in[25];
    const float* ln_b  = (const float*)d_in[26];

    float* sctx   = symp(g_short);
    float* mctx   = symp(g_mid);
    float* lctx   = symp(g_long);
    float* memc   = symp(g_memc);
    float* change = symp(g_change);
    float* fused  = symp(g_fused);
    float* xg     = symp(g_xg);
    float* h1     = symp(g_h1);
    float* fh     = symp(g_fh);

    // multi-scale conv + LN
    ctx_kernel<<<NTOK, 512>>>(emb, w_s, b_s, gs, bes, w_m, b_m, gm, bem,
                              w_l, b_l, gl, bel, sctx, mctx, lctx);

    // xg = emb @ W_ih^T + b_ih
    gemm_bf16_kernel<false><<<dim3(12, 128), 256>>>(emb, W_ih, b_ih, xg, NTOK, 1536, 512);

    // change path
    {
        SegPtrs sp{};
        sp.p[0] = emb; sp.p[1] = emb;
        seg_gemm_bf16_kernel<true, true><<<dim3(2, 128), 256>>>(sp, ce_w1, ce_b1, h1,
                                                                NTOK, 256, 1024);
    }
    gemm_bf16_kernel<false><<<dim3(4, 128), 256>>>(h1, ce_w2, ce_b2, change, NTOK, 512, 256);

    // GRU recurrence: cluster path if 16-CTA clusters supported, else legacy.
    reset_kernel<<<1, 256>>>();
    {
        cudaFuncSetAttribute(gru_cluster_kernel,
                             cudaFuncAttributeNonPortableClusterSizeAllowed, 1);
        cudaLaunchConfig_t cfg = {};
        cfg.gridDim = dim3(GRU_CTAS, 1, 1);
        cfg.blockDim = dim3(256, 1, 1);
        cfg.dynamicSmemBytes = 0;
        cfg.stream = 0;
        cudaLaunchAttribute attrs[1];
        attrs[0].id = cudaLaunchAttributeClusterDimension;
        attrs[0].val.clusterDim.x = 16;
        attrs[0].val.clusterDim.y = 1;
        attrs[0].val.clusterDim.z = 1;
        cfg.attrs = attrs;
        cfg.numAttrs = 1;

        int nclust = 0;
        cudaError_t qe = cudaOccupancyMaxActiveClusters(&nclust, gru_cluster_kernel, &cfg);
        if (qe != cudaSuccess) { (void)cudaGetLastError(); nclust = 0; }

        if (nclust >= 1) {
            cudaLaunchKernelEx(&cfg, gru_cluster_kernel, xg, W_hh, b_hh, memc);
        } else {
            gru_kernel<<<GRU_CTAS, 256>>>(xg, W_hh, b_hh, memc);
        }
    }

    // fusion path
    {
        SegPtrs sp{};
        sp.p[0] = emb; sp.p[1] = sctx; sp.p[2] = mctx; sp.p[3] = lctx; sp.p[4] = memc;
        seg_gemm_bf16_kernel<true, false><<<dim3(8, 128), 256>>>(sp, fu_w1, fu_b1, fh,
                                                                 NTOK, 1024, 2560);
    }
    gemm_bf16_kernel<false><<<dim3(4, 128), 256>>>(fh, fu_w2, fu_b2, fused, NTOK, 512, 1024);

    // out = LN(emb + fused + change)
    final_kernel<<<NTOK, 512>>>(emb, fused, change, ln_g, ln_b, (float*)d_out);
}

// round 11
// speedup vs baseline: 2.8501x; 1.0754x over previous
#include <cuda_runtime.h>
#include <cuda_bf16.h>
#include <math.h>
#include <stdint.h>

#define BQ 8
#define TQ 2048
#define DQ 512
#define NTOK (BQ * TQ)            // 16384
#define GRU_CTAS 128

// weight element counts / offsets in the split-bf16 scratch
#define W_IH_E  (1536 * 512)
#define CE1_E   (256 * 1024)
#define CE2_E   (512 * 256)
#define FU1_E   (1024 * 2560)
#define FU2_E   (512 * 1024)
#define O_WIH   0
#define O_CE1   (O_WIH + W_IH_E)
#define O_CE2   (O_CE1 + CE1_E)
#define O_FU1   (O_CE2 + CE2_E)
#define O_FU2   (O_FU1 + FU1_E)
#define W_TOT   (O_FU2 + FU2_E)

// ---------------- scratch (device globals; allocation-free) ----------------
__device__ float g_short[NTOK * DQ];
__device__ float g_mid[NTOK * DQ];
__device__ float g_long[NTOK * DQ];
__device__ float g_memc[NTOK * DQ];
__device__ float g_change[NTOK * DQ];
__device__ float g_fused[NTOK * DQ];
__device__ float g_xg[NTOK * 3 * DQ];
__device__ float g_h1[NTOK * 256];
__device__ float g_fh[NTOK * 1024];
__device__ float g_hbuf[2][BQ * DQ];
__device__ __nv_bfloat16 g_wh[W_TOT];
__device__ __nv_bfloat16 g_wl[W_TOT];
__device__ unsigned g_grp[16];              // legacy tree barrier
__device__ unsigned g_root;
__device__ volatile unsigned g_sense;

struct SegPtrs { const float* p[5]; };

// ---------------- helpers ----------------
__device__ __forceinline__ float gelu_exact(float x) {
    return 0.5f * x * (1.0f + erff(x * 0.70710678118654752440f));
}

#define FMA2(d, a, b) asm("fma.rn.f32x2 %0, %1, %2, %0;" : "+l"(d) : "l"(a), "l"(b))

__device__ __forceinline__ unsigned long long pack2(float x, float y) {
    unsigned long long r;
    asm("mov.b64 %0, {%1, %2};" : "=l"(r) : "r"(__float_as_uint(x)), "r"(__float_as_uint(y)));
    return r;
}
__device__ __forceinline__ void unpack2(unsigned long long v, float& x, float& y) {
    unsigned lo, hi;
    asm("mov.b64 {%0, %1}, %2;" : "=r"(lo), "=r"(hi) : "l"(v));
    x = __uint_as_float(lo); y = __uint_as_float(hi);
}

__device__ __forceinline__ float block_sum_512(float v, float* red) {
    int lane = threadIdx.x & 31, w = threadIdx.x >> 5;
    #pragma unroll
    for (int off = 16; off > 0; off >>= 1) v += __shfl_xor_sync(0xffffffffu, v, off);
    if (lane == 0) red[w] = v;
    __syncthreads();
    float s = (threadIdx.x < 16) ? red[threadIdx.x] : 0.0f;
    if (w == 0) {
        #pragma unroll
        for (int off = 8; off > 0; off >>= 1) s += __shfl_xor_sync(0xffffffffu, s, off);
        if (lane == 0) red[0] = s;
    }
    __syncthreads();
    float r = red[0];
    __syncthreads();
    return r;
}

__device__ __forceinline__ uint32_t smem_u32(const void* p) {
    return (uint32_t)__cvta_generic_to_shared(p);
}

__device__ __forceinline__ uint32_t my_ctarank() {
    uint32_t r; asm("mov.u32 %0, %%cluster_ctarank;" : "=r"(r)); return r;
}

__device__ __forceinline__ void st_cluster_f32(uint32_t local_smem_addr, int peer, float v) {
    uint32_t remote;
    asm volatile("mapa.shared::cluster.u32 %0, %1, %2;"
                 : "=r"(remote) : "r"(local_smem_addr), "r"(peer));
    asm volatile("st.shared::cluster.f32 [%0], %1;" :: "r"(remote), "f"(v) : "memory");
}

#define MBARRIER_INIT(mbar_smem_addr, count) \
    asm volatile("mbarrier.init.shared.b64 [%0], %1;" \
                 :: "r"((uint32_t)(mbar_smem_addr)), "r"((uint32_t)(count)) : "memory")

__device__ __forceinline__ void mbar_arrive_peer(uint32_t local_mbar_addr, int peer) {
    uint32_t rem;
    asm volatile("mapa.shared::cluster.u32 %0, %1, %2;"
                 : "=r"(rem) : "r"(local_mbar_addr), "r"(peer));
    asm volatile("mbarrier.arrive.shared::cluster.b64 _, [%0];"
                 :: "r"(rem) : "memory");
}

__device__ __forceinline__ void mbar_wait_parity(uint32_t mbar_addr, uint32_t parity) {
    asm volatile(
        "{\n\t"
        ".reg .pred P1;\n\t"
        "WAIT_LOOP_%=:\n\t"
        "mbarrier.try_wait.parity.acquire.cta.shared::cta.b64 P1, [%0], %1, 0x989680;\n\t"
        "@P1 bra.uni WAIT_DONE_%=;\n\t"
        "bra.uni WAIT_LOOP_%=;\n\t"
        "WAIT_DONE_%=:\n\t"
        "}"
        :: "r"(mbar_addr), "r"(parity) : "memory");
}

#define CLUSTER_BARRIER_ARRIVE() \
    asm volatile("barrier.cluster.arrive.aligned;" ::: "memory")
#define CLUSTER_BARRIER_WAIT() \
    asm volatile("barrier.cluster.wait.aligned;" ::: "memory")

#define LDSM4(r0, r1, r2, r3, addr) \
    asm volatile("ldmatrix.sync.aligned.m8n8.x4.shared.b16 {%0,%1,%2,%3},[%4];" \
                 : "=r"(r0), "=r"(r1), "=r"(r2), "=r"(r3) : "r"(addr))

#define MMA16816(d, a, b) \
    asm volatile("mma.sync.aligned.m16n8k16.row.col.f32.bf16.bf16.f32 " \
                 "{%0,%1,%2,%3},{%4,%5,%6,%7},{%8,%9},{%0,%1,%2,%3};" \
                 : "+f"((d)[0]), "+f"((d)[1]), "+f"((d)[2]), "+f"((d)[3]) \
                 : "r"((a)[0]), "r"((a)[1]), "r"((a)[2]), "r"((a)[3]), \
                   "r"((b)[0]), "r"((b)[1]))

#define CP_ASYNC16(dst, src) \
    asm volatile("cp.async.ca.shared.global [%0], [%1], 16;" \
                 :: "r"(dst), "l"(src) : "memory")
#define CP_ASYNC_COMMIT() asm volatile("cp.async.commit_group;" ::: "memory")
#define CP_ASYNC_WAIT0()  asm volatile("cp.async.wait_group 0;" ::: "memory")

__device__ __forceinline__ void split4(float4 v, __nv_bfloat16* hi, __nv_bfloat16* lo) {
    float x[4] = {v.x, v.y, v.z, v.w};
    #pragma unroll
    for (int i = 0; i < 4; i++) {
        __nv_bfloat16 h = __float2bfloat16(x[i]);
        hi[i] = h;
        lo[i] = __float2bfloat16(x[i] - __bfloat162float(h));
    }
}

__device__ __forceinline__ float fast_sigmoid(float x) {
    return __fdividef(1.0f, 1.0f + __expf(-x));
}
__device__ __forceinline__ float fast_tanh(float x) {
    return 2.0f * __fdividef(1.0f, 1.0f + __expf(-2.0f * x)) - 1.0f;
}

// ---------------- weight split prepass ----------------
__global__ void convert_w_kernel(const float* __restrict__ src,
                                 __nv_bfloat16* __restrict__ dh,
                                 __nv_bfloat16* __restrict__ dl, int n) {
    int i = blockIdx.x * 256 + threadIdx.x;
    if (i < n) {
        float x = src[i];
        __nv_bfloat16 h = __float2bfloat16(x);
        dh[i] = h;
        dl[i] = __float2bfloat16(x - __bfloat162float(h));
    }
}

// ---------------- conv (3 scales) + per-scale LN, fused ----------------
__global__ void ctx_kernel(const float* __restrict__ emb,
                           const float* __restrict__ w_s, const float* __restrict__ b_s,
                           const float* __restrict__ g_s, const float* __restrict__ be_s,
                           const float* __restrict__ w_m, const float* __restrict__ b_m,
                           const float* __restrict__ g_m, const float* __restrict__ be_m,
                           const float* __restrict__ w_l, const float* __restrict__ b_l,
                           const float* __restrict__ g_l, const float* __restrict__ be_l,
                           float* __restrict__ out_s, float* __restrict__ out_m,
                           float* __restrict__ out_l) {
    __shared__ float red[16];
    const int token = blockIdx.x;
    const int t = token & (TQ - 1);
    const int d = threadIdx.x;

    float xr[32];
    #pragma unroll
    for (int j = 0; j < 32; j++)
        xr[j] = (t - j >= 0) ? emb[((size_t)(token - j)) * DQ + d] : 0.0f;

    float ys = b_s[d], ym = b_m[d], yl = b_l[d];
    #pragma unroll
    for (int j = 0; j < 2; j++)  ys += w_s[d * 2 + 1 - j] * xr[j];
    #pragma unroll
    for (int j = 0; j < 8; j++)  ym += w_m[d * 8 + 7 - j] * xr[j];
    #pragma unroll
    for (int j = 0; j < 32; j++) yl += w_l[d * 32 + 31 - j] * xr[j];

    const size_t base = (size_t)token * DQ + d;
    {
        float mu = block_sum_512(ys, red) * (1.0f / DQ);
        float dv = ys - mu;
        float var = block_sum_512(dv * dv, red) * (1.0f / DQ);
        out_s[base] = dv * rsqrtf(var + 1e-5f) * g_s[d] + be_s[d];
    }
    {
        float mu = block_sum_512(ym, red) * (1.0f / DQ);
        float dv = ym - mu;
        float var = block_sum_512(dv * dv, red) * (1.0f / DQ);
        out_m[base] = dv * rsqrtf(var + 1e-5f) * g_m[d] + be_m[d];
    }
    {
        float mu = block_sum_512(yl, red) * (1.0f / DQ);
        float dv = yl - mu;
        float var = block_sum_512(dv * dv, red) * (1.0f / DQ);
        out_l[base] = dv * rsqrtf(var + 1e-5f) * g_l[d] + be_l[d];
    }
}

// ============================================================================
// Pipelined tensor-core GEMM. A fp32 (register-staged + split in kernel);
// W pre-split bf16 hi/lo (cp.async, 2-stage double buffer).
// BM=BN=128, BK=32, 256 thr, warp tile 32x64, 3-pass split MMA.
// ============================================================================
struct GemmSmemP {
    __nv_bfloat16 Ah[128][40];         // 10240 B
    __nv_bfloat16 Al[128][40];         // 10240 B
    __nv_bfloat16 Bh[2][128][40];      // 20480 B
    __nv_bfloat16 Bl[2][128][40];      // 20480 B
};
#define GEMM_SMEM_BYTES ((int)sizeof(GemmSmemP))   // 61440

__device__ __forceinline__ void gemm_mainloop_k32(
    const __nv_bfloat16 Ah[128][40], const __nv_bfloat16 Al[128][40],
    const __nv_bfloat16 Bh[128][40], const __nv_bfloat16 Bl[128][40],
    float acc[2][8][4], int warp_m, int warp_n, int lane) {
    #pragma unroll
    for (int ks = 0; ks < 32; ks += 16) {
        const int arow = (lane & 15);
        const int acol = ks + (lane >> 4) * 8;
        uint32_t ah[2][4], al[2][4];
        #pragma unroll
        for (int mi = 0; mi < 2; mi++) {
            int mb = warp_m * 32 + mi * 16;
            LDSM4(ah[mi][0], ah[mi][1], ah[mi][2], ah[mi][3],
                  smem_u32(&Ah[mb + arow][acol]));
            LDSM4(al[mi][0], al[mi][1], al[mi][2], al[mi][3],
                  smem_u32(&Al[mb + arow][acol]));
        }
        #pragma unroll
        for (int pair = 0; pair < 4; pair++) {
            int nb = warp_n * 64 + pair * 16;
            uint32_t bh[4], bl[4];
            LDSM4(bh[0], bh[1], bh[2], bh[3], smem_u32(&Bh[nb + arow][acol]));
            LDSM4(bl[0], bl[1], bl[2], bl[3], smem_u32(&Bl[nb + arow][acol]));
            uint32_t bEh[2] = {bh[0], bh[2]}, bOh[2] = {bh[1], bh[3]};
            uint32_t bEl[2] = {bl[0], bl[2]}, bOl[2] = {bl[1], bl[3]};
            #pragma unroll
            for (int mi = 0; mi < 2; mi++) {
                MMA16816(acc[mi][2 * pair],     ah[mi], bEh);
                MMA16816(acc[mi][2 * pair],     ah[mi], bEl);
                MMA16816(acc[mi][2 * pair],     al[mi], bEh);
                MMA16816(acc[mi][2 * pair + 1], ah[mi], bOh);
                MMA16816(acc[mi][2 * pair + 1], ah[mi], bOl);
                MMA16816(acc[mi][2 * pair + 1], al[mi], bOh);
            }
        }
    }
}

template <bool GELU>
__device__ __forceinline__ void gemm_epilogue(
    float acc[2][8][4], const float* __restrict__ bias, float* __restrict__ C,
    int N, int m0, int n0, int warp_m, int warp_n, int lane) {
    const int g = lane >> 2, tg = lane & 3;
    #pragma unroll
    for (int mi = 0; mi < 2; mi++) {
        #pragma unroll
        for (int ni = 0; ni < 8; ni++) {
            int row = m0 + warp_m * 32 + mi * 16 + g;
            int col = n0 + warp_n * 64 + ni * 8 + tg * 2;
            float b0 = bias[col], b1 = bias[col + 1];
            float v0 = acc[mi][ni][0] + b0, v1 = acc[mi][ni][1] + b1;
            float v2 = acc[mi][ni][2] + b0, v3 = acc[mi][ni][3] + b1;
            if (GELU) {
                v0 = gelu_exact(v0); v1 = gelu_exact(v1);
                v2 = gelu_exact(v2); v3 = gelu_exact(v3);
            }
            *reinterpret_cast<float2*>(&C[(size_t)row * N + col]) = make_float2(v0, v1);
            *reinterpret_cast<float2*>(&C[(size_t)(row + 8) * N + col]) = make_float2(v2, v3);
        }
    }
}

// issue cp.async for the B tile at k0 into the given stage
__device__ __forceinline__ void issue_b(
    GemmSmemP& sm, const __nv_bfloat16* __restrict__ Wh,
    const __nv_bfloat16* __restrict__ Wl, int n0, int k0, int K, int stage, int tid) {
    #pragma unroll
    for (int v = 0; v < 2; v++) {
        int f = v * 256 + tid;
        int r = f >> 2, c8 = (f & 3) * 8;
        size_t src = (size_t)(n0 + r) * K + k0 + c8;
        CP_ASYNC16(smem_u32(&sm.Bh[stage][r][c8]), Wh + src);
        CP_ASYNC16(smem_u32(&sm.Bl[stage][r][c8]), Wl + src);
    }
}

template <bool GELU>
__global__ __launch_bounds__(256)
void gemm_bf16_kernel(const float* __restrict__ A,
                      const __nv_bfloat16* __restrict__ Wh,
                      const __nv_bfloat16* __restrict__ Wl,
                      const float* __restrict__ bias, float* __restrict__ C,
                      int M, int N, int K) {
    extern __shared__ char dynsm[];
    GemmSmemP& sm = *reinterpret_cast<GemmSmemP*>(dynsm);
    const int tid = threadIdx.x;
    const int lane = tid & 31, wid = tid >> 5;
    const int warp_m = wid >> 1, warp_n = wid & 1;
    const int m0 = blockIdx.y * 128, n0 = blockIdx.x * 128;

    float acc[2][8][4];
    #pragma unroll
    for (int mi = 0; mi < 2; mi++)
        #pragma unroll
        for (int ni = 0; ni < 8; ni++)
            #pragma unroll
            for (int j = 0; j < 4; j++) acc[mi][ni][j] = 0.0f;

    // prologue: A tile 0 -> regs; B tile 0 -> cp.async stage 0
    float4 avr[4];
    #pragma unroll
    for (int v = 0; v < 4; v++) {
        int f = v * 256 + tid;
        int r = f >> 3, c4 = (f & 7) << 2;
        avr[v] = *reinterpret_cast<const float4*>(A + (size_t)(m0 + r) * K + c4);
    }
    issue_b(sm, Wh, Wl, n0, 0, K, 0, tid);
    CP_ASYNC_COMMIT();

    int stage = 0;
    for (int k0 = 0; k0 < K; k0 += 32) {
        // split-store staged A regs
        #pragma unroll
        for (int v = 0; v < 4; v++) {
            int f = v * 256 + tid;
            int r = f >> 3, c4 = (f & 7) << 2;
            split4(avr[v], &sm.Ah[r][c4], &sm.Al[r][c4]);
        }
        CP_ASYNC_WAIT0();
        __syncthreads();
        if (k0 + 32 < K) {
            #pragma unroll
            for (int v = 0; v < 4; v++) {
                int f = v * 256 + tid;
                int r = f >> 3, c4 = (f & 7) << 2;
                avr[v] = *reinterpret_cast<const float4*>(
                    A + (size_t)(m0 + r) * K + k0 + 32 + c4);
            }
            issue_b(sm, Wh, Wl, n0, k0 + 32, K, stage ^ 1, tid);
            CP_ASYNC_COMMIT();
        }
        gemm_mainloop_k32(sm.Ah, sm.Al, sm.Bh[stage], sm.Bl[stage],
                          acc, warp_m, warp_n, lane);
        __syncthreads();
        stage ^= 1;
    }
    gemm_epilogue<GELU>(acc, bias, C, N, m0, n0, warp_m, warp_n, lane);
}

// Segmented variant: logical A = concat of 512-wide segments (no copy buffer).
template <bool GELU, bool PREV>
__global__ __launch_bounds__(256)
void seg_gemm_bf16_kernel(SegPtrs segs,
                          const __nv_bfloat16* __restrict__ Wh,
                          const __nv_bfloat16* __restrict__ Wl,
                          const float* __restrict__ bias, float* __restrict__ C,
                          int M, int N, int K) {
    extern __shared__ char dynsm[];
    GemmSmemP& sm = *reinterpret_cast<GemmSmemP*>(dynsm);
    const int tid = threadIdx.x;
    const int lane = tid & 31, wid = tid >> 5;
    const int warp_m = wid >> 1, warp_n = wid & 1;
    const int m0 = blockIdx.y * 128, n0 = blockIdx.x * 128;

    float acc[2][8][4];
    #pragma unroll
    for (int mi = 0; mi < 2; mi++)
        #pragma unroll
        for (int ni = 0; ni < 8; ni++)
            #pragma unroll
            for (int j = 0; j < 4; j++) acc[mi][ni][j] = 0.0f;

    auto load_a = [&](int kk, float4* out) {
        const int seg = kk >> 9;
        const int ks = kk & 511;
        const float* __restrict__ Aseg = segs.p[seg];
        #pragma unroll
        for (int v = 0; v < 4; v++) {
            int f = v * 256 + tid;
            int r = f >> 3, c4 = (f & 7) << 2;
            int m = m0 + r;
            if (PREV && seg == 1) m = ((m & (TQ - 1)) == 0) ? m : m - 1;
            out[v] = *reinterpret_cast<const float4*>(Aseg + (size_t)m * DQ + ks + c4);
        }
    };

    float4 avr[4];
    load_a(0, avr);
    issue_b(sm, Wh, Wl, n0, 0, K, 0, tid);
    CP_ASYNC_COMMIT();

    int stage = 0;
    for (int k0 = 0; k0 < K; k0 += 32) {
        #pragma unroll
        for (int v = 0; v < 4; v++) {
            int f = v * 256 + tid;
            int r = f >> 3, c4 = (f & 7) << 2;
            split4(avr[v], &sm.Ah[r][c4], &sm.Al[r][c4]);
        }
        CP_ASYNC_WAIT0();
        __syncthreads();
        if (k0 + 32 < K) {
            load_a(k0 + 32, avr);
            issue_b(sm, Wh, Wl, n0, k0 + 32, K, stage ^ 1, tid);
            CP_ASYNC_COMMIT();
        }
        gemm_mainloop_k32(sm.Ah, sm.Al, sm.Bh[stage], sm.Bl[stage],
                          acc, warp_m, warp_n, lane);
        __syncthreads();
        stage ^= 1;
    }
    gemm_epilogue<GELU>(acc, bias, C, N, m0, n0, warp_m, warp_n, lane);
}

// ============================================================================
// GRU — cluster version with per-CTA mbarrier signaling (unchanged from R10)
// ============================================================================
__global__ void __launch_bounds__(256, 1)
gru_cluster_kernel(const float* __restrict__ xg, const float* __restrict__ W_hh,
                   const float* __restrict__ b_hh, float* __restrict__ memc) {
    __shared__ float hbuf[2][DQ];
    __shared__ float hg_sh[96];
    __shared__ float xg_sh[96];
    __shared__ __align__(8) unsigned long long mbar[2];

    const int tid = threadIdx.x;
    const int w = tid >> 5, lane = tid & 31;
    const int rank = (int)my_ctarank();
    const int batch = blockIdx.x >> 4;
    const int d0 = rank * 32;

    unsigned long long wreg[12][8];
    #pragma unroll
    for (int rl = 0; rl < 12; rl++) {
        int rr = w * 12 + rl;
        int g = rr >> 5, di = rr & 31;
        const float* wp = W_hh + (size_t)(g * DQ + d0 + di) * DQ;
        #pragma unroll
        for (int j = 0; j < 8; j++) {
            float2 v = *reinterpret_cast<const float2*>(wp + j * 64 + lane * 2);
            wreg[rl][j] = pack2(v.x, v.y);
        }
    }

    float bh_r = 0.f, bh_z = 0.f, bh_n = 0.f;
    if (tid < 64) {
        int l = tid & 31;
        bh_r = b_hh[d0 + l];
        bh_z = b_hh[DQ + d0 + l];
        bh_n = b_hh[2 * DQ + d0 + l];
    }

    const int xgi_g = tid >> 5, xgi_i = tid & 31;
    const size_t xg_stride = 3 * DQ;
    const size_t xg_base0 = (size_t)(batch * TQ) * xg_stride + xgi_g * DQ + d0 + xgi_i;

    if (tid == 0) {
        MBARRIER_INIT(smem_u32(&mbar[0]), 16);
        MBARRIER_INIT(smem_u32(&mbar[1]), 16);
    }
    hbuf[0][tid] = 0.f;
    hbuf[0][tid + 256] = 0.f;
    __syncthreads();
    CLUSTER_BARRIER_ARRIVE();
    CLUSTER_BARRIER_WAIT();

    float xv_cur = 0.f;
    if (tid < 96) xv_cur = xg[xg_base0];
    int ph0 = 0, ph1 = 0;

    for (int t = 0; t < TQ; t++) {
        float xv_next = 0.f;
        if (tid < 96 && t + 1 < TQ) xv_next = xg[xg_base0 + (size_t)(t + 1) * xg_stride];

        if (t > 0) {
            if (t & 1) { mbar_wait_parity(smem_u32(&mbar[1]), (uint32_t)ph1); ph1 ^= 1; }
            else       { mbar_wait_parity(smem_u32(&mbar[0]), (uint32_t)ph0); ph0 ^= 1; }
        }

        const float* hcur = hbuf[t & 1];
        unsigned long long acc[12];
        #pragma unroll
        for (int rl = 0; rl < 12; rl++) acc[rl] = 0ull;
        #pragma unroll
        for (int j = 0; j < 8; j++) {
            unsigned long long h2 =
                *reinterpret_cast<const unsigned long long*>(&hcur[j * 64 + lane * 2]);
            #pragma unroll
            for (int rl = 0; rl < 12; rl++) FMA2(acc[rl], h2, wreg[rl][j]);
        }
        #pragma unroll
        for (int rl = 0; rl < 12; rl++) {
            float x, y;
            unpack2(acc[rl], x, y);
            float s = x + y;
            #pragma unroll
            for (int off = 16; off > 0; off >>= 1)
                s += __shfl_xor_sync(0xffffffffu, s, off);
            if (lane == 0) hg_sh[w * 12 + rl] = s;
        }
        if (tid < 96) xg_sh[tid] = xv_cur;
        __syncthreads();

        float hnew = 0.f;
        if (tid < 64) {
            int l = tid & 31;
            float hr = hg_sh[l] + bh_r;
            float hz = hg_sh[32 + l] + bh_z;
            float hn = hg_sh[64 + l] + bh_n;
            float r = fast_sigmoid(xg_sh[l] + hr);
            float z = fast_sigmoid(xg_sh[32 + l] + hz);
            float n = fast_tanh(xg_sh[64 + l] + r * hn);
            float hold = hcur[d0 + l];
            hnew = (1.0f - z) * n + z * hold;
        }
        if (tid >= 32 && tid < 64)
            memc[(size_t)(batch * TQ + t) * DQ + d0 + (tid & 31)] = hnew;
        if (tid < 32 && t + 1 < TQ) {
            uint32_t dst = smem_u32(&hbuf[(t + 1) & 1][d0 + tid]);
            #pragma unroll
            for (int p = 0; p < 16; p++) st_cluster_f32(dst, p, hnew);
        }
        __syncthreads();

        if (tid < 16 && t + 1 < TQ)
            mbar_arrive_peer(smem_u32(&mbar[(t + 1) & 1]), tid);

        xv_cur = xv_next;
    }
    CLUSTER_BARRIER_ARRIVE();
    CLUSTER_BARRIER_WAIT();
}

// ---------------- legacy GRU (fallback; tree barrier) ----------------
__global__ void __launch_bounds__(256)
gru_kernel(const float* __restrict__ xg, const float* __restrict__ W_hh,
           const float* __restrict__ b_hh, float* __restrict__ memc) {
    __shared__ float h_sh[BQ * DQ];
    __shared__ float hg_sh[BQ * 12];

    const int tid = threadIdx.x;
    const int w = tid >> 5, lane = tid & 31;
    const int bp = w & 1, rh = w >> 1;
    const int d0 = blockIdx.x * 4;

    unsigned long long wreg[3][8];
    #pragma unroll
    for (int rl = 0; rl < 3; rl++) {
        int lr = rh * 3 + rl;
        int grow = (lr >> 2) * DQ + d0 + (lr & 3);
        const float* wp = W_hh + (size_t)grow * DQ;
        #pragma unroll
        for (int j = 0; j < 8; j++) {
            float2 v = *reinterpret_cast<const float2*>(wp + j * 64 + lane * 2);
            wreg[rl][j] = pack2(v.x, v.y);
        }
    }

    for (int t = 0; t < TQ; t++) {
        const float* hin = g_hbuf[t & 1];
        float* hout = g_hbuf[(t + 1) & 1];

        const float4* hp = reinterpret_cast<const float4*>(hin);
        #pragma unroll
        for (int v = 0; v < 4; v++)
            reinterpret_cast<float4*>(h_sh)[tid + v * 256] = hp[tid + v * 256];

        float xr = 0.f, xz = 0.f, xn = 0.f;
        if (tid < 32) {
            int b = tid >> 2, i = tid & 3;
            size_t base = ((size_t)(b * TQ + t)) * (3 * DQ) + d0 + i;
            xr = xg[base];
            xz = xg[base + DQ];
            xn = xg[base + 2 * DQ];
        }
        __syncthreads();

        unsigned long long acc[3][4];
        #pragma unroll
        for (int rl = 0; rl < 3; rl++)
            #pragma unroll
            for (int bb = 0; bb < 4; bb++) acc[rl][bb] = 0ull;

        #pragma unroll
        for (int j = 0; j < 8; j++) {
            unsigned long long h2[4];
            #pragma unroll
            for (int bb = 0; bb < 4; bb++)
                h2[bb] = *reinterpret_cast<const unsigned long long*>(
                    &h_sh[(bp * 4 + bb) * DQ + j * 64 + lane * 2]);
            #pragma unroll
            for (int rl = 0; rl < 3; rl++)
                #pragma unroll
                for (int bb = 0; bb < 4; bb++)
                    FMA2(acc[rl][bb], h2[bb], wreg[rl][j]);
        }

        #pragma unroll
        for (int rl = 0; rl < 3; rl++)
            #pragma unroll
            for (int bb = 0; bb < 4; bb++) {
                float x, y;
                unpack2(acc[rl][bb], x, y);
                float s = x + y;
                #pragma unroll
                for (int off = 16; off > 0; off >>= 1)
                    s += __shfl_xor_sync(0xffffffffu, s, off);
                if (lane == 0) hg_sh[(bp * 4 + bb) * 12 + rh * 3 + rl] = s;
            }
        __syncthreads();

        if (tid < 32) {
            int b = tid >> 2, i = tid & 3;
            int d = d0 + i;
            float hr = hg_sh[b * 12 + i]     + b_hh[d];
            float hz = hg_sh[b * 12 + 4 + i] + b_hh[DQ + d];
            float hn = hg_sh[b * 12 + 8 + i] + b_hh[2 * DQ + d];
            float r = 1.0f / (1.0f + expf(-(xr + hr)));
            float z = 1.0f / (1.0f + expf(-(xz + hz)));
            float n = tanhf(xn + r * hn);
            float hold = h_sh[b * DQ + d];
            float hnew = (1.0f - z) * n + z * hold;
            hout[b * DQ + d] = hnew;
            memc[((size_t)(b * TQ + t)) * DQ + d] = hnew;
        }
        __syncthreads();

        if (tid == 0) {
            __threadfence();
            const unsigned step = (unsigned)(t + 1);
            const int g = blockIdx.x >> 3;
            unsigned a = atomicAdd(&g_grp[g], 1u) + 1u;
            if (a == step * 8u) {
                unsigned r = atomicAdd(&g_root, 1u) + 1u;
                if (r == step * 16u) {
                    g_sense = step;
                }
            }
            int spins = 0;
            while (g_sense < step) {
                if (++spins > 32) __nanosleep(32);
            }
            __threadfence();
        }
        __syncthreads();
    }
}

__global__ void reset_kernel() {
    int tid = threadIdx.x;
    for (int i = tid; i < BQ * DQ; i += blockDim.x) {
        g_hbuf[0][i] = 0.0f;
        g_hbuf[1][i] = 0.0f;
    }
    if (tid < 16) g_grp[tid] = 0u;
    if (tid == 0) { g_root = 0u; g_sense = 0u; }
}

// ---------------- final residual + LN ----------------
__global__ void final_kernel(const float* __restrict__ emb, const float* __restrict__ fused,
                             const float* __restrict__ change,
                             const float* __restrict__ ln_g, const float* __restrict__ ln_b,
                             float* __restrict__ out) {
    __shared__ float red[16];
    const int token = blockIdx.x;
    const int d = threadIdx.x;
    const size_t base = (size_t)token * DQ + d;
    float x = emb[base] + fused[base] + change[base];
    float mu = block_sum_512(x, red) * (1.0f / DQ);
    float dv = x - mu;
    float var = block_sum_512(dv * dv, red) * (1.0f / DQ);
    out[base] = dv * rsqrtf(var + 1e-5f) * ln_g[d] + ln_b[d];
}

// ---------------- launch ----------------
static float* symp(const void* sym) {
    void* p = nullptr;
    cudaGetSymbolAddress(&p, sym);
    return (float*)p;
}

extern "C" void kernel_launch(void* const* d_in, const int* in_sizes, int n_in,
                              void* d_out, int out_size) {
    const float* emb   = (const float*)d_in[0];
    const float* w_s   = (const float*)d_in[1];
    const float* b_s   = (const float*)d_in[2];
    const float* gs    = (const float*)d_in[3];
    const float* bes   = (const float*)d_in[4];
    const float* w_m   = (const float*)d_in[5];
    const float* b_m   = (const float*)d_in[6];
    const float* gm    = (const float*)d_in[7];
    const float* bem   = (const float*)d_in[8];
    const float* w_l   = (const float*)d_in[9];
    const float* b_l   = (const float*)d_in[10];
    const float* gl    = (const float*)d_in[11];
    const float* bel   = (const float*)d_in[12];
    const float* W_ih  = (const float*)d_in[13];
    const float* W_hh  = (const float*)d_in[14];
    const float* b_ih  = (const float*)d_in[15];
    const float* b_hh  = (const float*)d_in[16];
    const float* ce_w1 = (const float*)d_in[17];
    const float* ce_b1 = (const float*)d_in[18];
    const float* ce_w2 = (const float*)d_in[19];
    const float* ce_b2 = (const float*)d_in[20];
    const float* fu_w1 = (const float*)d_in[21];
    const float* fu_b1 = (const float*)d_in[22];
    const float* fu_w2 = (const float*)d_in[23];
    const float* fu_b2 = (const float*)d_in[24];
    const float* ln_g  = (const float*)d_in[25];
    const float* ln_b  = (const float*)d_in[26];

    float* sctx   = symp(g_short);
    float* mctx   = symp(g_mid);
    float* lctx   = symp(g_long);
    float* memc   = symp(g_memc);
    float* change = symp(g_change);
    float* fused  = symp(g_fused);
    float* xg     = symp(g_xg);
    float* h1     = symp(g_h1);
    float* fh     = symp(g_fh);
    __nv_bfloat16* wh = (__nv_bfloat16*)symp(g_wh);
    __nv_bfloat16* wl = (__nv_bfloat16*)symp(g_wl);

    // weight split prepass
    convert_w_kernel<<<(W_IH_E + 255) / 256, 256>>>(W_ih, wh + O_WIH, wl + O_WIH, W_IH_E);
    convert_w_kernel<<<(CE1_E + 255) / 256, 256>>>(ce_w1, wh + O_CE1, wl + O_CE1, CE1_E);
    convert_w_kernel<<<(CE2_E + 255) / 256, 256>>>(ce_w2, wh + O_CE2, wl + O_CE2, CE2_E);
    convert_w_kernel<<<(FU1_E + 255) / 256, 256>>>(fu_w1, wh + O_FU1, wl + O_FU1, FU1_E);
    convert_w_kernel<<<(FU2_E + 255) / 256, 256>>>(fu_w2, wh + O_FU2, wl + O_FU2, FU2_E);

    // raise dynamic smem limits (host-side, capture-safe)
    cudaFuncSetAttribute(gemm_bf16_kernel<false>,
                         cudaFuncAttributeMaxDynamicSharedMemorySize, GEMM_SMEM_BYTES);
    cudaFuncSetAttribute(seg_gemm_bf16_kernel<true, true>,
                         cudaFuncAttributeMaxDynamicSharedMemorySize, GEMM_SMEM_BYTES);
    cudaFuncSetAttribute(seg_gemm_bf16_kernel<true, false>,
                         cudaFuncAttributeMaxDynamicSharedMemorySize, GEMM_SMEM_BYTES);

    // multi-scale conv + LN
    ctx_kernel<<<NTOK, 512>>>(emb, w_s, b_s, gs, bes, w_m, b_m, gm, bem,
                              w_l, b_l, gl, bel, sctx, mctx, lctx);

    // xg = emb @ W_ih^T + b_ih
    gemm_bf16_kernel<false><<<dim3(12, 128), 256, GEMM_SMEM_BYTES>>>(
        emb, wh + O_WIH, wl + O_WIH, b_ih, xg, NTOK, 1536, 512);

    // change path
    {
        SegPtrs sp{};
        sp.p[0] = emb; sp.p[1] = emb;
        seg_gemm_bf16_kernel<true, true><<<dim3(2, 128), 256, GEMM_SMEM_BYTES>>>(
            sp, wh + O_CE1, wl + O_CE1, ce_b1, h1, NTOK, 256, 1024);
    }
    gemm_bf16_kernel<false><<<dim3(4, 128), 256, GEMM_SMEM_BYTES>>>(
        h1, wh + O_CE2, wl + O_CE2, ce_b2, change, NTOK, 512, 256);

    // GRU recurrence: cluster path if 16-CTA clusters supported, else legacy.
    reset_kernel<<<1, 256>>>();
    {
        cudaFuncSetAttribute(gru_cluster_kernel,
                             cudaFuncAttributeNonPortableClusterSizeAllowed, 1);
        cudaLaunchConfig_t cfg = {};
        cfg.gridDim = dim3(GRU_CTAS, 1, 1);
        cfg.blockDim = dim3(256, 1, 1);
        cfg.dynamicSmemBytes = 0;
        cfg.stream = 0;
        cudaLaunchAttribute attrs[1];
        attrs[0].id = cudaLaunchAttributeClusterDimension;
        attrs[0].val.clusterDim.x = 16;
        attrs[0].val.clusterDim.y = 1;
        attrs[0].val.clusterDim.z = 1;
        cfg.attrs = attrs;
        cfg.numAttrs = 1;

        int nclust = 0;
        cudaError_t qe = cudaOccupancyMaxActiveClusters(&nclust, gru_cluster_kernel, &cfg);
        if (qe != cudaSuccess) { (void)cudaGetLastError(); nclust = 0; }

        if (nclust >= 1) {
            cudaLaunchKernelEx(&cfg, gru_cluster_kernel, xg, W_hh, b_hh, memc);
        } else {
            gru_kernel<<<GRU_CTAS, 256>>>(xg, W_hh, b_hh, memc);
        }
    }

    // fusion path
    {
        SegPtrs sp{};
        sp.p[0] = emb; sp.p[1] = sctx; sp.p[2] = mctx; sp.p[3] = lctx; sp.p[4] = memc;
        seg_gemm_bf16_kernel<true, false><<<dim3(8, 128), 256, GEMM_SMEM_BYTES>>>(
            sp, wh + O_FU1, wl + O_FU1, fu_b1, fh, NTOK, 1024, 2560);
    }
    gemm_bf16_kernel<false><<<dim3(4, 128), 256, GEMM_SMEM_BYTES>>>(
        fh, wh + O_FU2, wl + O_FU2, fu_b2, fused, NTOK, 512, 1024);

    // out = LN(emb + fused + change)
    final_kernel<<<NTOK, 512>>>(emb, fused, change, ln_g, ln_b, (float*)d_out);
}